// round 2
// baseline (speedup 1.0000x reference)
#include <cuda_runtime.h>
#include <math.h>

#define BB 4
#define SS 2048
#define DD 1024
#define HH 16
#define HDD 64
#define M_TOT (BB*SS)   // 8192

// Scratch (allocation-free: __device__ globals)
__device__ float g_q[(size_t)BB*HH*SS*HDD];
__device__ float g_k[(size_t)BB*HH*SS*HDD];
__device__ float g_v[(size_t)BB*HH*SS*HDD];
__device__ float g_attn[(size_t)BB*SS*DD];

// ---------------------------------------------------------------------------
// GEMM: C = A[M x 1024] @ W[1024 x 1024], 128x128x16 tiles, 8x8 microtiles.
// SPLIT=true  -> store into [B,H,S,HD] head-split layout (for Q/K/V).
// SPLIT=false -> plain row-major [M x 1024].
// ---------------------------------------------------------------------------
template<bool SPLIT>
__global__ void __launch_bounds__(256) gemm128(const float* __restrict__ A,
                                               const float* __restrict__ W,
                                               float* __restrict__ C) {
    __shared__ float As[16][128];   // transposed: As[k][m]
    __shared__ float Bs[16][128];   // Bs[k][n]

    const int tid = threadIdx.x;
    const int tx  = tid & 15;
    const int ty  = tid >> 4;
    const int m0  = blockIdx.y * 128;
    const int n0  = blockIdx.x * 128;

    float acc[8][8];
#pragma unroll
    for (int i = 0; i < 8; i++)
#pragma unroll
        for (int j = 0; j < 8; j++) acc[i][j] = 0.f;

    for (int kt = 0; kt < 1024; kt += 16) {
        // stage A tile (transposed) and B tile
#pragma unroll
        for (int u = 0; u < 2; u++) {
            int l   = tid + u * 256;
            int row = l >> 2;             // 0..127
            int k4  = (l & 3) << 2;       // 0,4,8,12
            float4 a = *(const float4*)&A[(size_t)(m0 + row) * 1024 + kt + k4];
            As[k4 + 0][row] = a.x;
            As[k4 + 1][row] = a.y;
            As[k4 + 2][row] = a.z;
            As[k4 + 3][row] = a.w;
            int kr = l >> 5;              // 0..15
            int n4 = (l & 31) << 2;       // 0..124
            *(float4*)&Bs[kr][n4] =
                *(const float4*)&W[(size_t)(kt + kr) * 1024 + n0 + n4];
        }
        __syncthreads();

#pragma unroll
        for (int k = 0; k < 16; k++) {
            float a[8], b[8];
            *(float4*)&a[0] = *(float4*)&As[k][ty * 8];
            *(float4*)&a[4] = *(float4*)&As[k][ty * 8 + 4];
            *(float4*)&b[0] = *(float4*)&Bs[k][tx * 8];
            *(float4*)&b[4] = *(float4*)&Bs[k][tx * 8 + 4];
#pragma unroll
            for (int i = 0; i < 8; i++)
#pragma unroll
                for (int j = 0; j < 8; j++)
                    acc[i][j] = fmaf(a[i], b[j], acc[i][j]);
        }
        __syncthreads();
    }

    // epilogue
#pragma unroll
    for (int i = 0; i < 8; i++) {
        int m = m0 + ty * 8 + i;
#pragma unroll
        for (int jq = 0; jq < 2; jq++) {
            int n = n0 + tx * 8 + jq * 4;
            float4 v = make_float4(acc[i][jq * 4 + 0], acc[i][jq * 4 + 1],
                                   acc[i][jq * 4 + 2], acc[i][jq * 4 + 3]);
            if (SPLIT) {
                int b_  = m >> 11;        // / 2048
                int s_  = m & 2047;
                int h_  = n >> 6;
                int hd_ = n & 63;
                size_t idx = ((size_t)(b_ * HH + h_) * SS + s_) * HDD + hd_;
                *(float4*)&C[idx] = v;
            } else {
                *(float4*)&C[(size_t)m * 1024 + n] = v;
            }
        }
    }
}

// ---------------------------------------------------------------------------
// Fused attention: per (b,h, 64-query tile). Online softmax, keys limited to
// valid_len (exact: exp(-1e6 - m) == 0.0f in fp32, so skipping is bit-exact).
// ---------------------------------------------------------------------------
__global__ void __launch_bounds__(256) attn_kernel(const int* __restrict__ valid_lens,
                                                   float* __restrict__ out) {
    extern __shared__ float sm[];
    float (*Qs)[65] = (float(*)[65])sm;                 // 64 x 65
    float (*Ks)[65] = (float(*)[65])(sm + 64 * 65);     // 64 x 65
    float (*Ps)[65] = (float(*)[65])(sm + 2 * 64 * 65); // 64 x 65
    float (*Vs)[64] = (float(*)[64])(sm + 3 * 64 * 65); // 64 x 64

    const int qt = blockIdx.x;         // query tile 0..31
    const int bh = blockIdx.y;         // 0..63
    const int b  = bh >> 4;
    const int h  = bh & 15;
    const int vlen = valid_lens[b];

    const float* q = g_q + (size_t)bh * (SS * HDD);
    const float* k = g_k + (size_t)bh * (SS * HDD);
    const float* v = g_v + (size_t)bh * (SS * HDD);

    const int tid = threadIdx.x;
    const int tx = tid & 15, ty = tid >> 4;
    const int r0 = ty * 4, c0 = tx * 4;

    // stage Q tile
#pragma unroll
    for (int u = 0; u < 4; u++) {
        int l = tid + u * 256;         // 0..1023
        int r = l >> 4;
        int j = (l & 15) << 2;
        float4 t4 = *(const float4*)&q[(size_t)(qt * 64 + r) * HDD + j];
        Qs[r][j] = t4.x; Qs[r][j + 1] = t4.y; Qs[r][j + 2] = t4.z; Qs[r][j + 3] = t4.w;
    }

    float m_i[4], l_i[4], O[4][4];
#pragma unroll
    for (int rr = 0; rr < 4; rr++) {
        m_i[rr] = -1e30f;
        l_i[rr] = 0.f;
#pragma unroll
        for (int dd = 0; dd < 4; dd++) O[rr][dd] = 0.f;
    }

    const int ntiles = (vlen + 63) >> 6;
    for (int kt = 0; kt < ntiles; kt++) {
        __syncthreads();   // previous PV done before overwriting tiles
#pragma unroll
        for (int u = 0; u < 4; u++) {
            int l = tid + u * 256;
            int r = l >> 4;
            int j = (l & 15) << 2;
            float4 t4 = *(const float4*)&k[(size_t)(kt * 64 + r) * HDD + j];
            Ks[r][j] = t4.x; Ks[r][j + 1] = t4.y; Ks[r][j + 2] = t4.z; Ks[r][j + 3] = t4.w;
            *(float4*)&Vs[r][j] = *(const float4*)&v[(size_t)(kt * 64 + r) * HDD + j];
        }
        __syncthreads();

        // S = Q K^T (4x4 per thread)
        float s[4][4];
#pragma unroll
        for (int rr = 0; rr < 4; rr++)
#pragma unroll
            for (int cc = 0; cc < 4; cc++) s[rr][cc] = 0.f;

#pragma unroll
        for (int kk = 0; kk < 64; kk++) {
            float qv[4], kv[4];
#pragma unroll
            for (int rr = 0; rr < 4; rr++) qv[rr] = Qs[r0 + rr][kk];
#pragma unroll
            for (int cc = 0; cc < 4; cc++) kv[cc] = Ks[c0 + cc][kk];
#pragma unroll
            for (int rr = 0; rr < 4; rr++)
#pragma unroll
                for (int cc = 0; cc < 4; cc++)
                    s[rr][cc] = fmaf(qv[rr], kv[cc], s[rr][cc]);
        }

        // scale + mask
#pragma unroll
        for (int cc = 0; cc < 4; cc++) {
            bool masked = (kt * 64 + c0 + cc) >= vlen;
#pragma unroll
            for (int rr = 0; rr < 4; rr++)
                s[rr][cc] = masked ? -1e30f : s[rr][cc] * 0.125f;
        }

        // online softmax update
#pragma unroll
        for (int rr = 0; rr < 4; rr++) {
            float mloc = fmaxf(fmaxf(s[rr][0], s[rr][1]), fmaxf(s[rr][2], s[rr][3]));
#pragma unroll
            for (int off = 8; off > 0; off >>= 1)
                mloc = fmaxf(mloc, __shfl_xor_sync(0xffffffffu, mloc, off));
            float m_new = fmaxf(m_i[rr], mloc);
            float scl = __expf(m_i[rr] - m_new);
            m_i[rr] = m_new;
            float psum = 0.f;
#pragma unroll
            for (int cc = 0; cc < 4; cc++) {
                float p = __expf(s[rr][cc] - m_new);
                Ps[r0 + rr][c0 + cc] = p;
                psum += p;
            }
#pragma unroll
            for (int off = 8; off > 0; off >>= 1)
                psum += __shfl_xor_sync(0xffffffffu, psum, off);
            l_i[rr] = l_i[rr] * scl + psum;
#pragma unroll
            for (int dd = 0; dd < 4; dd++) O[rr][dd] *= scl;
        }
        __syncthreads();

        // O += P @ V
#pragma unroll 4
        for (int c = 0; c < 64; c++) {
            float4 vv = *(const float4*)&Vs[c][c0];
#pragma unroll
            for (int rr = 0; rr < 4; rr++) {
                float p = Ps[r0 + rr][c];
                O[rr][0] = fmaf(p, vv.x, O[rr][0]);
                O[rr][1] = fmaf(p, vv.y, O[rr][1]);
                O[rr][2] = fmaf(p, vv.z, O[rr][2]);
                O[rr][3] = fmaf(p, vv.w, O[rr][3]);
            }
        }
    }

    // normalize + store merged-head layout [B,S,D]
#pragma unroll
    for (int rr = 0; rr < 4; rr++) {
        float inv = 1.f / l_i[rr];
        int s_ = qt * 64 + r0 + rr;
        float4 o4 = make_float4(O[rr][0] * inv, O[rr][1] * inv,
                                O[rr][2] * inv, O[rr][3] * inv);
        *(float4*)&out[((size_t)b * SS + s_) * DD + h * HDD + c0] = o4;
    }
}

// ---------------------------------------------------------------------------
extern "C" void kernel_launch(void* const* d_in, const int* in_sizes, int n_in,
                              void* d_out, int out_size) {
    const float* queries    = (const float*)d_in[0];
    const float* keys       = (const float*)d_in[1];
    const float* values     = (const float*)d_in[2];
    const int*   valid_lens = (const int*)  d_in[3];
    const float* Wq         = (const float*)d_in[4];
    const float* Wk         = (const float*)d_in[5];
    const float* Wv         = (const float*)d_in[6];
    const float* Wo         = (const float*)d_in[7];
    float* out = (float*)d_out;

    float *pq, *pk, *pv, *pa;
    cudaGetSymbolAddress((void**)&pq, g_q);
    cudaGetSymbolAddress((void**)&pk, g_k);
    cudaGetSymbolAddress((void**)&pv, g_v);
    cudaGetSymbolAddress((void**)&pa, g_attn);

    dim3 ggrid(1024 / 128, M_TOT / 128);   // (8, 64)
    dim3 gblk(256);

    // QKV projections (store head-split)
    gemm128<true><<<ggrid, gblk>>>(queries, Wq, pq);
    gemm128<true><<<ggrid, gblk>>>(keys,    Wk, pk);
    gemm128<true><<<ggrid, gblk>>>(values,  Wv, pv);

    // fused masked attention
    const int smem = (3 * 64 * 65 + 64 * 64) * sizeof(float);  // 66304 B
    cudaFuncSetAttribute(attn_kernel, cudaFuncAttributeMaxDynamicSharedMemorySize, smem);
    dim3 agrid(SS / 64, BB * HH);          // (32, 64)
    attn_kernel<<<agrid, gblk, smem>>>(valid_lens, pa);

    // output projection
    gemm128<false><<<ggrid, gblk>>>(pa, Wo, out);
}

// round 4
// speedup vs baseline: 1.4528x; 1.4528x over previous
#include <cuda_runtime.h>
#include <cuda_bf16.h>
#include <math.h>
#include <stdint.h>

#define BB 4
#define SS 2048
#define DD 1024
#define HH 16
#define HDD 64
#define M_TOT (BB*SS)   // 8192
#define GK 3072         // split-3 K
#define BKC 32          // k per chunk
#define NCHUNKS (GK/BKC) // 96
#define ASTRIDE 40      // bf16 elems per smem row (80B, conflict-free)

// ---------------------------------------------------------------------------
// scratch (__device__ globals; allocation-free)
// ---------------------------------------------------------------------------
__device__ float g_q[(size_t)BB*HH*SS*HDD];
__device__ float g_k[(size_t)BB*HH*SS*HDD];
__device__ float g_v[(size_t)BB*HH*SS*HDD];
__device__ float g_attn[(size_t)BB*SS*DD];
__device__ __nv_bfloat16 g_abig[(size_t)M_TOT*GK];   // [8192 x 3072] = hi|hi|lo
__device__ __nv_bfloat16 g_wbig[(size_t)DD*GK];      // [1024(n) x 3072] = Wh|Wl|Wh

// ---------------------------------------------------------------------------
// conversion: A [8192x1024] f32 -> Abig [8192x3072] bf16 (hi|hi|lo)
// ---------------------------------------------------------------------------
__global__ void __launch_bounds__(256) convert_a(const float4* __restrict__ A,
                                                 __nv_bfloat162* __restrict__ out) {
    int idx = blockIdx.x * 256 + threadIdx.x;
    int row = idx >> 8;
    int c4  = idx & 255;
    float4 a = A[idx];
    __nv_bfloat162 h0 = __floats2bfloat162_rn(a.x, a.y);
    __nv_bfloat162 h1 = __floats2bfloat162_rn(a.z, a.w);
    float lx = a.x - __low2float(h0);
    float ly = a.y - __high2float(h0);
    float lz = a.z - __low2float(h1);
    float lw = a.w - __high2float(h1);
    __nv_bfloat162 l0 = __floats2bfloat162_rn(lx, ly);
    __nv_bfloat162 l1 = __floats2bfloat162_rn(lz, lw);
    size_t base = (size_t)row * 1536;
    out[base + c4*2 + 0]        = h0;
    out[base + c4*2 + 1]        = h1;
    out[base + 512 + c4*2 + 0]  = h0;
    out[base + 512 + c4*2 + 1]  = h1;
    out[base + 1024 + c4*2 + 0] = l0;
    out[base + 1024 + c4*2 + 1] = l1;
}

// W [1024(k) x 1024(n)] f32 -> Wbig [1024(n) x 3072(k')] bf16 (Wh|Wl|Wh), transposed
__global__ void __launch_bounds__(1024) convert_w(const float* __restrict__ W,
                                                  __nv_bfloat16* __restrict__ out) {
    __shared__ float t[32][33];
    int k0 = blockIdx.y * 32, n0 = blockIdx.x * 32;
    t[threadIdx.y][threadIdx.x] = W[(size_t)(k0 + threadIdx.y) * 1024 + n0 + threadIdx.x];
    __syncthreads();
    float v = t[threadIdx.x][threadIdx.y];
    int n = n0 + threadIdx.y, k = k0 + threadIdx.x;
    __nv_bfloat16 hi = __float2bfloat16(v);
    __nv_bfloat16 lo = __float2bfloat16(v - __bfloat162float(hi));
    out[(size_t)n * GK + k]        = hi;
    out[(size_t)n * GK + 1024 + k] = lo;
    out[(size_t)n * GK + 2048 + k] = hi;
}

// ---------------------------------------------------------------------------
// PTX helpers (baseline PTX only — no arch-feature suffixed instructions)
// ---------------------------------------------------------------------------
__device__ __forceinline__ uint32_t smem_u32(const void* p) {
    return (uint32_t)__cvta_generic_to_shared(p);
}
__device__ __forceinline__ void cp16(uint32_t dst, const void* src) {
    asm volatile("cp.async.cg.shared.global [%0], [%1], 16;" :: "r"(dst), "l"(src));
}
__device__ __forceinline__ void cp_commit() {
    asm volatile("cp.async.commit_group;" ::: "memory");
}
template<int N>
__device__ __forceinline__ void cp_wait() {
    asm volatile("cp.async.wait_group %0;" :: "n"(N) : "memory");
}
__device__ __forceinline__ void ldsm4(uint32_t& r0, uint32_t& r1, uint32_t& r2, uint32_t& r3,
                                      uint32_t addr) {
    asm volatile("ldmatrix.sync.aligned.m8n8.x4.shared.b16 {%0,%1,%2,%3}, [%4];"
                 : "=r"(r0), "=r"(r1), "=r"(r2), "=r"(r3) : "r"(addr));
}
__device__ __forceinline__ void mma16816(float* c, const uint32_t* a, const uint32_t* b) {
    asm volatile("mma.sync.aligned.m16n8k16.row.col.f32.bf16.bf16.f32 "
                 "{%0,%1,%2,%3}, {%4,%5,%6,%7}, {%8,%9}, {%0,%1,%2,%3};"
                 : "+f"(c[0]), "+f"(c[1]), "+f"(c[2]), "+f"(c[3])
                 : "r"(a[0]), "r"(a[1]), "r"(a[2]), "r"(a[3]), "r"(b[0]), "r"(b[1]));
}

// ---------------------------------------------------------------------------
// HMMA GEMM: C[m,n] = sum_k A[m,k]*B[n,k]; M=8192, N=1024, K=3072 (bf16->f32)
// CTA 128x128, BK=32, 8 warps (2m x 4n), warp tile 64x32.
// ---------------------------------------------------------------------------
template<bool SPLIT>
__global__ void __launch_bounds__(256) gemm_tc(const __nv_bfloat16* __restrict__ A,
                                               const __nv_bfloat16* __restrict__ B,
                                               float* __restrict__ C) {
    __shared__ __nv_bfloat16 As[2][128 * ASTRIDE];
    __shared__ __nv_bfloat16 Bs[2][128 * ASTRIDE];

    const int tid  = threadIdx.x;
    const int lane = tid & 31;
    const int warp = tid >> 5;
    const int wm   = warp & 1;          // 0..1
    const int wn   = warp >> 1;         // 0..3
    const int m0   = blockIdx.y * 128;
    const int n0   = blockIdx.x * 128;

    const __nv_bfloat16* Arow = A + (size_t)m0 * GK;
    const __nv_bfloat16* Brow = B + (size_t)n0 * GK;

    // load task: 2 per tile (A and B each): row = task>>2 (0..127), seg = task&3
    const int t0row = tid >> 1;            // wait: 512 tasks over 256 thr = 2 each
    (void)t0row;

    auto load_chunk = [&](int buf, int c) {
        const size_t kof = (size_t)c * BKC;
#pragma unroll
        for (int u = 0; u < 2; u++) {
            int task = tid + u * 256;      // 0..511
            int row  = task >> 2;
            int seg  = task & 3;
            uint32_t so = (uint32_t)(row * ASTRIDE + seg * 8) * 2;   // bytes
            cp16(smem_u32(&As[buf][0]) + so, Arow + (size_t)row * GK + kof + seg * 8);
            cp16(smem_u32(&Bs[buf][0]) + so, Brow + (size_t)row * GK + kof + seg * 8);
        }
        cp_commit();
    };

    float acc[4][4][4];
#pragma unroll
    for (int i = 0; i < 4; i++)
#pragma unroll
        for (int j = 0; j < 4; j++)
#pragma unroll
            for (int r = 0; r < 4; r++) acc[i][j][r] = 0.f;

    load_chunk(0, 0);

    for (int c = 0; c < NCHUNKS; c++) {
        const int buf = c & 1;
        if (c + 1 < NCHUNKS) {
            load_chunk(buf ^ 1, c + 1);
            cp_wait<1>();
        } else {
            cp_wait<0>();
        }
        __syncthreads();

        const uint32_t sA = smem_u32(&As[buf][0]);
        const uint32_t sB = smem_u32(&Bs[buf][0]);
#pragma unroll
        for (int k16 = 0; k16 < 2; k16++) {
            const uint32_t kb = k16 * 32;   // 16 bf16 = 32 bytes
            uint32_t a[4][4];
#pragma unroll
            for (int mf = 0; mf < 4; mf++) {
                uint32_t addr = sA + (uint32_t)((wm * 64 + mf * 16 + (lane & 15)) * ASTRIDE) * 2
                              + kb + (lane >> 4) * 16;
                ldsm4(a[mf][0], a[mf][1], a[mf][2], a[mf][3], addr);
            }
            uint32_t b[4][2];
#pragma unroll
            for (int bb = 0; bb < 2; bb++) {
                uint32_t nrow = wn * 32 + bb * 16 + ((lane >> 4) & 1) * 8 + (lane & 7);
                uint32_t addr = sB + nrow * (ASTRIDE * 2) + kb + ((lane >> 3) & 1) * 16;
                uint32_t r0, r1, r2, r3;
                ldsm4(r0, r1, r2, r3, addr);
                b[bb * 2 + 0][0] = r0; b[bb * 2 + 0][1] = r1;
                b[bb * 2 + 1][0] = r2; b[bb * 2 + 1][1] = r3;
            }
#pragma unroll
            for (int mf = 0; mf < 4; mf++)
#pragma unroll
                for (int nf = 0; nf < 4; nf++)
                    mma16816(acc[mf][nf], a[mf], b[nf]);
        }
        __syncthreads();
    }

    // epilogue: c0,c1 -> (row grp, col 2*tg, +1); c2,c3 -> row grp+8
    const int grp = lane >> 2;
    const int tg  = lane & 3;
#pragma unroll
    for (int mf = 0; mf < 4; mf++) {
#pragma unroll
        for (int nf = 0; nf < 4; nf++) {
            int n = n0 + wn * 32 + nf * 8 + tg * 2;
#pragma unroll
            for (int half = 0; half < 2; half++) {
                int m = m0 + wm * 64 + mf * 16 + grp + half * 8;
                float2 v = make_float2(acc[mf][nf][half * 2], acc[mf][nf][half * 2 + 1]);
                if (SPLIT) {
                    int b_ = m >> 11, s_ = m & 2047;
                    int h_ = n >> 6,  hd = n & 63;
                    *(float2*)&C[((size_t)(b_ * HH + h_) * SS + s_) * HDD + hd] = v;
                } else {
                    *(float2*)&C[(size_t)m * DD + n] = v;
                }
            }
        }
    }
}

// ---------------------------------------------------------------------------
// fused masked attention (unchanged; exact vlen skip)
// ---------------------------------------------------------------------------
__global__ void __launch_bounds__(256) attn_kernel(const int* __restrict__ valid_lens,
                                                   float* __restrict__ out) {
    extern __shared__ float smf[];
    float (*Qs)[65] = (float(*)[65])smf;
    float (*Ks)[65] = (float(*)[65])(smf + 64 * 65);
    float (*Ps)[65] = (float(*)[65])(smf + 2 * 64 * 65);
    float (*Vs)[64] = (float(*)[64])(smf + 3 * 64 * 65);

    const int qt = blockIdx.x;
    const int bh = blockIdx.y;
    const int b  = bh >> 4;
    const int h  = bh & 15;
    const int vlen = valid_lens[b];

    const float* q = g_q + (size_t)bh * (SS * HDD);
    const float* k = g_k + (size_t)bh * (SS * HDD);
    const float* v = g_v + (size_t)bh * (SS * HDD);

    const int tid = threadIdx.x;
    const int tx = tid & 15, ty = tid >> 4;
    const int r0 = ty * 4, c0 = tx * 4;

#pragma unroll
    for (int u = 0; u < 4; u++) {
        int l = tid + u * 256;
        int r = l >> 4;
        int j = (l & 15) << 2;
        float4 t4 = *(const float4*)&q[(size_t)(qt * 64 + r) * HDD + j];
        Qs[r][j] = t4.x; Qs[r][j+1] = t4.y; Qs[r][j+2] = t4.z; Qs[r][j+3] = t4.w;
    }

    float m_i[4], l_i[4], O[4][4];
#pragma unroll
    for (int rr = 0; rr < 4; rr++) {
        m_i[rr] = -1e30f; l_i[rr] = 0.f;
#pragma unroll
        for (int dd = 0; dd < 4; dd++) O[rr][dd] = 0.f;
    }

    const int ntiles = (vlen + 63) >> 6;
    for (int kt = 0; kt < ntiles; kt++) {
        __syncthreads();
#pragma unroll
        for (int u = 0; u < 4; u++) {
            int l = tid + u * 256;
            int r = l >> 4;
            int j = (l & 15) << 2;
            float4 t4 = *(const float4*)&k[(size_t)(kt * 64 + r) * HDD + j];
            Ks[r][j] = t4.x; Ks[r][j+1] = t4.y; Ks[r][j+2] = t4.z; Ks[r][j+3] = t4.w;
            *(float4*)&Vs[r][j] = *(const float4*)&v[(size_t)(kt * 64 + r) * HDD + j];
        }
        __syncthreads();

        float s[4][4];
#pragma unroll
        for (int rr = 0; rr < 4; rr++)
#pragma unroll
            for (int cc = 0; cc < 4; cc++) s[rr][cc] = 0.f;

#pragma unroll
        for (int kk = 0; kk < 64; kk++) {
            float qv[4], kv[4];
#pragma unroll
            for (int rr = 0; rr < 4; rr++) qv[rr] = Qs[r0 + rr][kk];
#pragma unroll
            for (int cc = 0; cc < 4; cc++) kv[cc] = Ks[c0 + cc][kk];
#pragma unroll
            for (int rr = 0; rr < 4; rr++)
#pragma unroll
                for (int cc = 0; cc < 4; cc++)
                    s[rr][cc] = fmaf(qv[rr], kv[cc], s[rr][cc]);
        }

#pragma unroll
        for (int cc = 0; cc < 4; cc++) {
            bool masked = (kt * 64 + c0 + cc) >= vlen;
#pragma unroll
            for (int rr = 0; rr < 4; rr++)
                s[rr][cc] = masked ? -1e30f : s[rr][cc] * 0.125f;
        }

#pragma unroll
        for (int rr = 0; rr < 4; rr++) {
            float mloc = fmaxf(fmaxf(s[rr][0], s[rr][1]), fmaxf(s[rr][2], s[rr][3]));
#pragma unroll
            for (int off = 8; off > 0; off >>= 1)
                mloc = fmaxf(mloc, __shfl_xor_sync(0xffffffffu, mloc, off));
            float m_new = fmaxf(m_i[rr], mloc);
            float scl = __expf(m_i[rr] - m_new);
            m_i[rr] = m_new;
            float psum = 0.f;
#pragma unroll
            for (int cc = 0; cc < 4; cc++) {
                float p = __expf(s[rr][cc] - m_new);
                Ps[r0 + rr][c0 + cc] = p;
                psum += p;
            }
#pragma unroll
            for (int off = 8; off > 0; off >>= 1)
                psum += __shfl_xor_sync(0xffffffffu, psum, off);
            l_i[rr] = l_i[rr] * scl + psum;
#pragma unroll
            for (int dd = 0; dd < 4; dd++) O[rr][dd] *= scl;
        }
        __syncthreads();

#pragma unroll 4
        for (int c = 0; c < 64; c++) {
            float4 vv = *(const float4*)&Vs[c][c0];
#pragma unroll
            for (int rr = 0; rr < 4; rr++) {
                float p = Ps[r0 + rr][c];
                O[rr][0] = fmaf(p, vv.x, O[rr][0]);
                O[rr][1] = fmaf(p, vv.y, O[rr][1]);
                O[rr][2] = fmaf(p, vv.z, O[rr][2]);
                O[rr][3] = fmaf(p, vv.w, O[rr][3]);
            }
        }
    }

#pragma unroll
    for (int rr = 0; rr < 4; rr++) {
        float inv = 1.f / l_i[rr];
        int s_ = qt * 64 + r0 + rr;
        float4 o4 = make_float4(O[rr][0]*inv, O[rr][1]*inv, O[rr][2]*inv, O[rr][3]*inv);
        *(float4*)&out[((size_t)b * SS + s_) * DD + h * HDD + c0] = o4;
    }
}

// ---------------------------------------------------------------------------
extern "C" void kernel_launch(void* const* d_in, const int* in_sizes, int n_in,
                              void* d_out, int out_size) {
    (void)in_sizes; (void)n_in; (void)out_size;
    const float* queries    = (const float*)d_in[0];
    const float* keys       = (const float*)d_in[1];
    const float* values     = (const float*)d_in[2];
    const int*   valid_lens = (const int*)  d_in[3];
    const float* Wq         = (const float*)d_in[4];
    const float* Wk         = (const float*)d_in[5];
    const float* Wv         = (const float*)d_in[6];
    const float* Wo         = (const float*)d_in[7];
    float* out = (float*)d_out;

    float *pq, *pk, *pv, *pa;
    __nv_bfloat16 *pabig, *pwbig;
    cudaGetSymbolAddress((void**)&pq, g_q);
    cudaGetSymbolAddress((void**)&pk, g_k);
    cudaGetSymbolAddress((void**)&pv, g_v);
    cudaGetSymbolAddress((void**)&pa, g_attn);
    cudaGetSymbolAddress((void**)&pabig, g_abig);
    cudaGetSymbolAddress((void**)&pwbig, g_wbig);

    const int attn_smem = (3 * 64 * 65 + 64 * 64) * sizeof(float);
    cudaFuncSetAttribute(attn_kernel, cudaFuncAttributeMaxDynamicSharedMemorySize, attn_smem);

    dim3 cw_grid(32, 32), cw_blk(32, 32);
    dim3 ca_grid(M_TOT * DD / 4 / 256), ca_blk(256);
    dim3 gg(DD / 128, M_TOT / 128);   // (8, 64)
    dim3 gb(256);

    // Q projection
    convert_w<<<cw_grid, cw_blk>>>(Wq, pwbig);
    convert_a<<<ca_grid, ca_blk>>>((const float4*)queries, (__nv_bfloat162*)pabig);
    gemm_tc<true><<<gg, gb>>>(pabig, pwbig, pq);
    // K projection
    convert_w<<<cw_grid, cw_blk>>>(Wk, pwbig);
    convert_a<<<ca_grid, ca_blk>>>((const float4*)keys, (__nv_bfloat162*)pabig);
    gemm_tc<true><<<gg, gb>>>(pabig, pwbig, pk);
    // V projection
    convert_w<<<cw_grid, cw_blk>>>(Wv, pwbig);
    convert_a<<<ca_grid, ca_blk>>>((const float4*)values, (__nv_bfloat162*)pabig);
    gemm_tc<true><<<gg, gb>>>(pabig, pwbig, pv);

    // fused masked attention
    dim3 agrid(SS / 64, BB * HH);
    attn_kernel<<<agrid, 256, attn_smem>>>(valid_lens, pa);

    // output projection
    convert_w<<<cw_grid, cw_blk>>>(Wo, pwbig);
    convert_a<<<ca_grid, ca_blk>>>((const float4*)pa, (__nv_bfloat162*)pabig);
    gemm_tc<false><<<gg, gb>>>(pabig, pwbig, out);
}

// round 5
// speedup vs baseline: 1.6586x; 1.1416x over previous
#include <cuda_runtime.h>
#include <math.h>
#include <stdint.h>

#define BB 4
#define SS 2048
#define DD 1024
#define HH 16
#define HDD 64
#define M_TOT (BB*SS)     // 8192
#define GKP 1024          // projection K
#define BK 16             // k per chunk (tf32)
#define NCH (GKP/BK)      // 64
#define STR 20            // f32 per smem row (80B, conflict-free ldmatrix)

// ---------------------------------------------------------------------------
// scratch (__device__ globals; allocation-free)
// ---------------------------------------------------------------------------
__device__ float g_q[(size_t)BB*HH*SS*HDD];
__device__ float g_k[(size_t)BB*HH*SS*HDD];
__device__ float g_v[(size_t)BB*HH*SS*HDD];
__device__ float g_attn[(size_t)BB*SS*DD];
__device__ float g_wt[(size_t)DD*DD];     // transposed weight [n][k] f32

// ---------------------------------------------------------------------------
// W [1024(k) x 1024(n)] -> WT [1024(n) x 1024(k)]
// ---------------------------------------------------------------------------
__global__ void __launch_bounds__(1024) transpose_w(const float* __restrict__ W,
                                                    float* __restrict__ WT) {
    __shared__ float t[32][33];
    int k0 = blockIdx.y * 32, n0 = blockIdx.x * 32;
    t[threadIdx.y][threadIdx.x] = W[(size_t)(k0 + threadIdx.y) * 1024 + n0 + threadIdx.x];
    __syncthreads();
    WT[(size_t)(n0 + threadIdx.y) * 1024 + k0 + threadIdx.x] = t[threadIdx.x][threadIdx.y];
}

// ---------------------------------------------------------------------------
// PTX helpers (baseline PTX, sm_80-level only)
// ---------------------------------------------------------------------------
__device__ __forceinline__ uint32_t smem_u32(const void* p) {
    return (uint32_t)__cvta_generic_to_shared(p);
}
__device__ __forceinline__ void cp16(uint32_t dst, const void* src) {
    asm volatile("cp.async.cg.shared.global [%0], [%1], 16;" :: "r"(dst), "l"(src));
}
__device__ __forceinline__ void cp_commit() {
    asm volatile("cp.async.commit_group;" ::: "memory");
}
template<int N>
__device__ __forceinline__ void cp_wait() {
    asm volatile("cp.async.wait_group %0;" :: "n"(N) : "memory");
}
__device__ __forceinline__ void ldsm4(uint32_t& r0, uint32_t& r1, uint32_t& r2, uint32_t& r3,
                                      uint32_t addr) {
    asm volatile("ldmatrix.sync.aligned.m8n8.x4.shared.b16 {%0,%1,%2,%3}, [%4];"
                 : "=r"(r0), "=r"(r1), "=r"(r2), "=r"(r3) : "r"(addr));
}
__device__ __forceinline__ uint32_t to_tf32(uint32_t x) {
    uint32_t y;
    asm("cvt.rna.tf32.f32 %0, %1;" : "=r"(y) : "r"(x));
    return y;
}
__device__ __forceinline__ void mma_tf32(float* c, const uint32_t* a, const uint32_t* b) {
    asm volatile("mma.sync.aligned.m16n8k8.row.col.f32.tf32.tf32.f32 "
                 "{%0,%1,%2,%3}, {%4,%5,%6,%7}, {%8,%9}, {%0,%1,%2,%3};"
                 : "+f"(c[0]), "+f"(c[1]), "+f"(c[2]), "+f"(c[3])
                 : "r"(a[0]), "r"(a[1]), "r"(a[2]), "r"(a[3]), "r"(b[0]), "r"(b[1]));
}

// ---------------------------------------------------------------------------
// tf32 GEMM: C[m,n] = sum_k A[m,k]*B[n,k]; M=8192, N=1024, K=1024 (f32 in/out)
// CTA 128x128, BK=16, 8 warps (2m x 4n), warp tile 64x32.
// ---------------------------------------------------------------------------
template<bool SPLIT>
__global__ void __launch_bounds__(256) gemm32(const float* __restrict__ A,
                                              const float* __restrict__ B,
                                              float* __restrict__ C) {
    __shared__ float As[2][128 * STR];
    __shared__ float Bs[2][128 * STR];

    const int tid  = threadIdx.x;
    const int lane = tid & 31;
    const int warp = tid >> 5;
    const int wm   = warp & 1;
    const int wn   = warp >> 1;
    const int m0   = blockIdx.y * 128;
    const int n0   = blockIdx.x * 128;

    const float* Arow = A + (size_t)m0 * GKP;
    const float* Brow = B + (size_t)n0 * GKP;

    auto load_chunk = [&](int buf, int c) {
        const size_t kof = (size_t)c * BK;
#pragma unroll
        for (int u = 0; u < 2; u++) {
            int task = tid + u * 256;       // 0..511
            int row  = task >> 2;           // 0..127
            int seg  = task & 3;            // 4-float (16B) segments
            uint32_t so = (uint32_t)(row * STR + seg * 4) * 4;  // bytes
            cp16(smem_u32(&As[buf][0]) + so, Arow + (size_t)row * GKP + kof + seg * 4);
            cp16(smem_u32(&Bs[buf][0]) + so, Brow + (size_t)row * GKP + kof + seg * 4);
        }
        cp_commit();
    };

    float acc[4][4][4];
#pragma unroll
    for (int i = 0; i < 4; i++)
#pragma unroll
        for (int j = 0; j < 4; j++)
#pragma unroll
            for (int r = 0; r < 4; r++) acc[i][j][r] = 0.f;

    load_chunk(0, 0);

    for (int c = 0; c < NCH; c++) {
        const int buf = c & 1;
        if (c + 1 < NCH) {
            load_chunk(buf ^ 1, c + 1);
            cp_wait<1>();
        } else {
            cp_wait<0>();
        }
        __syncthreads();

        const uint32_t sA = smem_u32(&As[buf][0]);
        const uint32_t sB = smem_u32(&Bs[buf][0]);
#pragma unroll
        for (int k8 = 0; k8 < 2; k8++) {
            const uint32_t kb = k8 * 32;    // 8 tf32 = 32 bytes
            uint32_t a[4][4];
#pragma unroll
            for (int mf = 0; mf < 4; mf++) {
                uint32_t addr = sA + (uint32_t)((wm * 64 + mf * 16 + (lane & 15)) * STR) * 4
                              + (lane >> 4) * 16 + kb;
                ldsm4(a[mf][0], a[mf][1], a[mf][2], a[mf][3], addr);
                a[mf][0] = to_tf32(a[mf][0]); a[mf][1] = to_tf32(a[mf][1]);
                a[mf][2] = to_tf32(a[mf][2]); a[mf][3] = to_tf32(a[mf][3]);
            }
            uint32_t b[4][2];
#pragma unroll
            for (int bb = 0; bb < 2; bb++) {
                uint32_t nrow = wn * 32 + bb * 16 + ((lane >> 4) & 1) * 8 + (lane & 7);
                uint32_t addr = sB + nrow * (STR * 4) + ((lane >> 3) & 1) * 16 + kb;
                uint32_t r0, r1, r2, r3;
                ldsm4(r0, r1, r2, r3, addr);
                b[bb * 2 + 0][0] = to_tf32(r0); b[bb * 2 + 0][1] = to_tf32(r1);
                b[bb * 2 + 1][0] = to_tf32(r2); b[bb * 2 + 1][1] = to_tf32(r3);
            }
#pragma unroll
            for (int mf = 0; mf < 4; mf++)
#pragma unroll
                for (int nf = 0; nf < 4; nf++)
                    mma_tf32(acc[mf][nf], a[mf], b[nf]);
        }
        __syncthreads();
    }

    const int grp = lane >> 2;
    const int tg  = lane & 3;
#pragma unroll
    for (int mf = 0; mf < 4; mf++) {
#pragma unroll
        for (int nf = 0; nf < 4; nf++) {
            int n = n0 + wn * 32 + nf * 8 + tg * 2;
#pragma unroll
            for (int half = 0; half < 2; half++) {
                int m = m0 + wm * 64 + mf * 16 + grp + half * 8;
                float2 v = make_float2(acc[mf][nf][half * 2], acc[mf][nf][half * 2 + 1]);
                if (SPLIT) {
                    int b_ = m >> 11, s_ = m & 2047;
                    int h_ = n >> 6,  hd = n & 63;
                    *(float2*)&C[((size_t)(b_ * HH + h_) * SS + s_) * HDD + hd] = v;
                } else {
                    *(float2*)&C[(size_t)m * DD + n] = v;
                }
            }
        }
    }
}

// ---------------------------------------------------------------------------
// FMA-pipe exp (no MUFU): exp(x) via 2^t, degree-5 poly on [-0.5, 0.5]
// ---------------------------------------------------------------------------
__device__ __forceinline__ float fast_exp(float x) {
    float t = fmaxf(x * 1.4426950408889634f, -126.0f);
    int   i = __float2int_rn(t);
    float f = t - (float)i;
    float p = 1.3333558146428443e-3f;
    p = fmaf(p, f, 9.6181291076284771e-3f);
    p = fmaf(p, f, 5.5504108664821580e-2f);
    p = fmaf(p, f, 2.4022650695910072e-1f);
    p = fmaf(p, f, 6.9314718055994531e-1f);
    p = fmaf(p, f, 1.0f);
    return p * __int_as_float((i + 127) << 23);
}

// ---------------------------------------------------------------------------
// fused masked attention (exact vlen skip, poly exp)
// ---------------------------------------------------------------------------
__global__ void __launch_bounds__(256) attn_kernel(const int* __restrict__ valid_lens,
                                                   float* __restrict__ out) {
    extern __shared__ float smf[];
    float (*Qs)[65] = (float(*)[65])smf;
    float (*Ks)[65] = (float(*)[65])(smf + 64 * 65);
    float (*Ps)[65] = (float(*)[65])(smf + 2 * 64 * 65);
    float (*Vs)[64] = (float(*)[64])(smf + 3 * 64 * 65);

    const int qt = blockIdx.x;
    const int bh = blockIdx.y;
    const int b  = bh >> 4;
    const int h  = bh & 15;
    const int vlen = valid_lens[b];

    const float* q = g_q + (size_t)bh * (SS * HDD);
    const float* k = g_k + (size_t)bh * (SS * HDD);
    const float* v = g_v + (size_t)bh * (SS * HDD);

    const int tid = threadIdx.x;
    const int tx = tid & 15, ty = tid >> 4;
    const int r0 = ty * 4, c0 = tx * 4;

#pragma unroll
    for (int u = 0; u < 4; u++) {
        int l = tid + u * 256;
        int r = l >> 4;
        int j = (l & 15) << 2;
        float4 t4 = *(const float4*)&q[(size_t)(qt * 64 + r) * HDD + j];
        Qs[r][j] = t4.x; Qs[r][j+1] = t4.y; Qs[r][j+2] = t4.z; Qs[r][j+3] = t4.w;
    }

    float m_i[4], l_i[4], O[4][4];
#pragma unroll
    for (int rr = 0; rr < 4; rr++) {
        m_i[rr] = -1e30f; l_i[rr] = 0.f;
#pragma unroll
        for (int dd = 0; dd < 4; dd++) O[rr][dd] = 0.f;
    }

    const int ntiles = (vlen + 63) >> 6;
    for (int kt = 0; kt < ntiles; kt++) {
        __syncthreads();
#pragma unroll
        for (int u = 0; u < 4; u++) {
            int l = tid + u * 256;
            int r = l >> 4;
            int j = (l & 15) << 2;
            float4 t4 = *(const float4*)&k[(size_t)(kt * 64 + r) * HDD + j];
            Ks[r][j] = t4.x; Ks[r][j+1] = t4.y; Ks[r][j+2] = t4.z; Ks[r][j+3] = t4.w;
            *(float4*)&Vs[r][j] = *(const float4*)&v[(size_t)(kt * 64 + r) * HDD + j];
        }
        __syncthreads();

        float s[4][4];
#pragma unroll
        for (int rr = 0; rr < 4; rr++)
#pragma unroll
            for (int cc = 0; cc < 4; cc++) s[rr][cc] = 0.f;

#pragma unroll
        for (int kk = 0; kk < 64; kk++) {
            float qv[4], kv[4];
#pragma unroll
            for (int rr = 0; rr < 4; rr++) qv[rr] = Qs[r0 + rr][kk];
#pragma unroll
            for (int cc = 0; cc < 4; cc++) kv[cc] = Ks[c0 + cc][kk];
#pragma unroll
            for (int rr = 0; rr < 4; rr++)
#pragma unroll
                for (int cc = 0; cc < 4; cc++)
                    s[rr][cc] = fmaf(qv[rr], kv[cc], s[rr][cc]);
        }

#pragma unroll
        for (int cc = 0; cc < 4; cc++) {
            bool masked = (kt * 64 + c0 + cc) >= vlen;
#pragma unroll
            for (int rr = 0; rr < 4; rr++)
                s[rr][cc] = masked ? -1e30f : s[rr][cc] * 0.125f;
        }

#pragma unroll
        for (int rr = 0; rr < 4; rr++) {
            float mloc = fmaxf(fmaxf(s[rr][0], s[rr][1]), fmaxf(s[rr][2], s[rr][3]));
#pragma unroll
            for (int off = 8; off > 0; off >>= 1)
                mloc = fmaxf(mloc, __shfl_xor_sync(0xffffffffu, mloc, off));
            float m_new = fmaxf(m_i[rr], mloc);
            float scl = fast_exp(m_i[rr] - m_new);
            m_i[rr] = m_new;
            float psum = 0.f;
#pragma unroll
            for (int cc = 0; cc < 4; cc++) {
                float p = fast_exp(s[rr][cc] - m_new);
                Ps[r0 + rr][c0 + cc] = p;
                psum += p;
            }
#pragma unroll
            for (int off = 8; off > 0; off >>= 1)
                psum += __shfl_xor_sync(0xffffffffu, psum, off);
            l_i[rr] = l_i[rr] * scl + psum;
#pragma unroll
            for (int dd = 0; dd < 4; dd++) O[rr][dd] *= scl;
        }
        __syncthreads();

#pragma unroll 4
        for (int c = 0; c < 64; c++) {
            float4 vv = *(const float4*)&Vs[c][c0];
#pragma unroll
            for (int rr = 0; rr < 4; rr++) {
                float p = Ps[r0 + rr][c];
                O[rr][0] = fmaf(p, vv.x, O[rr][0]);
                O[rr][1] = fmaf(p, vv.y, O[rr][1]);
                O[rr][2] = fmaf(p, vv.z, O[rr][2]);
                O[rr][3] = fmaf(p, vv.w, O[rr][3]);
            }
        }
    }

#pragma unroll
    for (int rr = 0; rr < 4; rr++) {
        float inv = 1.f / l_i[rr];
        int s_ = qt * 64 + r0 + rr;
        float4 o4 = make_float4(O[rr][0]*inv, O[rr][1]*inv, O[rr][2]*inv, O[rr][3]*inv);
        *(float4*)&out[((size_t)b * SS + s_) * DD + h * HDD + c0] = o4;
    }
}

// ---------------------------------------------------------------------------
extern "C" void kernel_launch(void* const* d_in, const int* in_sizes, int n_in,
                              void* d_out, int out_size) {
    (void)in_sizes; (void)n_in; (void)out_size;
    const float* queries    = (const float*)d_in[0];
    const float* keys       = (const float*)d_in[1];
    const float* values     = (const float*)d_in[2];
    const int*   valid_lens = (const int*)  d_in[3];
    const float* Wq         = (const float*)d_in[4];
    const float* Wk         = (const float*)d_in[5];
    const float* Wv         = (const float*)d_in[6];
    const float* Wo         = (const float*)d_in[7];
    float* out = (float*)d_out;

    float *pq, *pk, *pv, *pa, *pwt;
    cudaGetSymbolAddress((void**)&pq, g_q);
    cudaGetSymbolAddress((void**)&pk, g_k);
    cudaGetSymbolAddress((void**)&pv, g_v);
    cudaGetSymbolAddress((void**)&pa, g_attn);
    cudaGetSymbolAddress((void**)&pwt, g_wt);

    const int attn_smem = (3 * 64 * 65 + 64 * 64) * sizeof(float);
    cudaFuncSetAttribute(attn_kernel, cudaFuncAttributeMaxDynamicSharedMemorySize, attn_smem);

    dim3 tw_grid(32, 32), tw_blk(32, 32);
    dim3 gg(DD / 128, M_TOT / 128);   // (8, 64)
    dim3 gb(256);

    // Q projection
    transpose_w<<<tw_grid, tw_blk>>>(Wq, pwt);
    gemm32<true><<<gg, gb>>>(queries, pwt, pq);
    // K projection
    transpose_w<<<tw_grid, tw_blk>>>(Wk, pwt);
    gemm32<true><<<gg, gb>>>(keys, pwt, pk);
    // V projection
    transpose_w<<<tw_grid, tw_blk>>>(Wv, pwt);
    gemm32<true><<<gg, gb>>>(values, pwt, pv);

    // fused masked attention
    dim3 agrid(SS / 64, BB * HH);
    attn_kernel<<<agrid, 256, attn_smem>>>(valid_lens, pa);

    // output projection
    transpose_w<<<tw_grid, tw_blk>>>(Wo, pwt);
    gemm32<false><<<gg, gb>>>(pa, pwt, out);
}

// round 6
// speedup vs baseline: 2.2093x; 1.3320x over previous
#include <cuda_runtime.h>
#include <math.h>
#include <stdint.h>

#define BB 4
#define SS 2048
#define DD 1024
#define HH 16
#define HDD 64
#define M_TOT (BB*SS)     // 8192
#define GKP 1024          // projection K
#define BK 16             // k per chunk (tf32 gemm)
#define NCH (GKP/BK)      // 64
#define STR 20            // f32 per smem row (80B) in gemm
#define ATS 68            // f32 per smem row (272B) in attention

// ---------------------------------------------------------------------------
// scratch (__device__ globals; allocation-free)
// ---------------------------------------------------------------------------
__device__ float g_q[(size_t)BB*HH*SS*HDD];
__device__ float g_k[(size_t)BB*HH*SS*HDD];
__device__ float g_v[(size_t)BB*HH*SS*HDD];
__device__ float g_attn[(size_t)BB*SS*DD];
__device__ float g_wt[(size_t)DD*DD];

// ---------------------------------------------------------------------------
__global__ void __launch_bounds__(1024) transpose_w(const float* __restrict__ W,
                                                    float* __restrict__ WT) {
    __shared__ float t[32][33];
    int k0 = blockIdx.y * 32, n0 = blockIdx.x * 32;
    t[threadIdx.y][threadIdx.x] = W[(size_t)(k0 + threadIdx.y) * 1024 + n0 + threadIdx.x];
    __syncthreads();
    WT[(size_t)(n0 + threadIdx.y) * 1024 + k0 + threadIdx.x] = t[threadIdx.x][threadIdx.y];
}

// ---------------------------------------------------------------------------
// PTX helpers (baseline sm_80-level PTX only)
// ---------------------------------------------------------------------------
__device__ __forceinline__ uint32_t smem_u32(const void* p) {
    return (uint32_t)__cvta_generic_to_shared(p);
}
__device__ __forceinline__ void cp16(uint32_t dst, const void* src) {
    asm volatile("cp.async.cg.shared.global [%0], [%1], 16;" :: "r"(dst), "l"(src));
}
__device__ __forceinline__ void cp_commit() {
    asm volatile("cp.async.commit_group;" ::: "memory");
}
template<int N>
__device__ __forceinline__ void cp_wait() {
    asm volatile("cp.async.wait_group %0;" :: "n"(N) : "memory");
}
__device__ __forceinline__ void ldsm4(uint32_t& r0, uint32_t& r1, uint32_t& r2, uint32_t& r3,
                                      uint32_t addr) {
    asm volatile("ldmatrix.sync.aligned.m8n8.x4.shared.b16 {%0,%1,%2,%3}, [%4];"
                 : "=r"(r0), "=r"(r1), "=r"(r2), "=r"(r3) : "r"(addr));
}
__device__ __forceinline__ uint32_t to_tf32(uint32_t x) {
    uint32_t y;
    asm("cvt.rna.tf32.f32 %0, %1;" : "=r"(y) : "r"(x));
    return y;
}
__device__ __forceinline__ float tf32r(float x) {
    return __uint_as_float(to_tf32(__float_as_uint(x)));
}
__device__ __forceinline__ void mma_tf32(float* c, const uint32_t* a, const uint32_t* b) {
    asm volatile("mma.sync.aligned.m16n8k8.row.col.f32.tf32.tf32.f32 "
                 "{%0,%1,%2,%3}, {%4,%5,%6,%7}, {%8,%9}, {%0,%1,%2,%3};"
                 : "+f"(c[0]), "+f"(c[1]), "+f"(c[2]), "+f"(c[3])
                 : "r"(a[0]), "r"(a[1]), "r"(a[2]), "r"(a[3]), "r"(b[0]), "r"(b[1]));
}

// ---------------------------------------------------------------------------
// tf32 GEMM: C[m,n] = sum_k A[m,k]*B[n,k]; M=8192, N=1024, K=1024 (f32 in/out)
// ---------------------------------------------------------------------------
template<bool SPLIT>
__global__ void __launch_bounds__(256) gemm32(const float* __restrict__ A,
                                              const float* __restrict__ B,
                                              float* __restrict__ C) {
    __shared__ float As[2][128 * STR];
    __shared__ float Bs[2][128 * STR];

    const int tid  = threadIdx.x;
    const int lane = tid & 31;
    const int warp = tid >> 5;
    const int wm   = warp & 1;
    const int wn   = warp >> 1;
    const int m0   = blockIdx.y * 128;
    const int n0   = blockIdx.x * 128;

    const float* Arow = A + (size_t)m0 * GKP;
    const float* Brow = B + (size_t)n0 * GKP;

    auto load_chunk = [&](int buf, int c) {
        const size_t kof = (size_t)c * BK;
#pragma unroll
        for (int u = 0; u < 2; u++) {
            int task = tid + u * 256;
            int row  = task >> 2;
            int seg  = task & 3;
            uint32_t so = (uint32_t)(row * STR + seg * 4) * 4;
            cp16(smem_u32(&As[buf][0]) + so, Arow + (size_t)row * GKP + kof + seg * 4);
            cp16(smem_u32(&Bs[buf][0]) + so, Brow + (size_t)row * GKP + kof + seg * 4);
        }
        cp_commit();
    };

    float acc[4][4][4];
#pragma unroll
    for (int i = 0; i < 4; i++)
#pragma unroll
        for (int j = 0; j < 4; j++)
#pragma unroll
            for (int r = 0; r < 4; r++) acc[i][j][r] = 0.f;

    load_chunk(0, 0);

    for (int c = 0; c < NCH; c++) {
        const int buf = c & 1;
        if (c + 1 < NCH) {
            load_chunk(buf ^ 1, c + 1);
            cp_wait<1>();
        } else {
            cp_wait<0>();
        }
        __syncthreads();

        const uint32_t sA = smem_u32(&As[buf][0]);
        const uint32_t sB = smem_u32(&Bs[buf][0]);
#pragma unroll
        for (int k8 = 0; k8 < 2; k8++) {
            const uint32_t kb = k8 * 32;
            uint32_t a[4][4];
#pragma unroll
            for (int mf = 0; mf < 4; mf++) {
                uint32_t addr = sA + (uint32_t)((wm * 64 + mf * 16 + (lane & 15)) * STR) * 4
                              + (lane >> 4) * 16 + kb;
                ldsm4(a[mf][0], a[mf][1], a[mf][2], a[mf][3], addr);
                a[mf][0] = to_tf32(a[mf][0]); a[mf][1] = to_tf32(a[mf][1]);
                a[mf][2] = to_tf32(a[mf][2]); a[mf][3] = to_tf32(a[mf][3]);
            }
            uint32_t b[4][2];
#pragma unroll
            for (int bb = 0; bb < 2; bb++) {
                uint32_t nrow = wn * 32 + bb * 16 + ((lane >> 4) & 1) * 8 + (lane & 7);
                uint32_t addr = sB + nrow * (STR * 4) + ((lane >> 3) & 1) * 16 + kb;
                uint32_t r0, r1, r2, r3;
                ldsm4(r0, r1, r2, r3, addr);
                b[bb * 2 + 0][0] = to_tf32(r0); b[bb * 2 + 0][1] = to_tf32(r1);
                b[bb * 2 + 1][0] = to_tf32(r2); b[bb * 2 + 1][1] = to_tf32(r3);
            }
#pragma unroll
            for (int mf = 0; mf < 4; mf++)
#pragma unroll
                for (int nf = 0; nf < 4; nf++)
                    mma_tf32(acc[mf][nf], a[mf], b[nf]);
        }
        __syncthreads();
    }

    const int grp = lane >> 2;
    const int tg  = lane & 3;
#pragma unroll
    for (int mf = 0; mf < 4; mf++) {
#pragma unroll
        for (int nf = 0; nf < 4; nf++) {
            int n = n0 + wn * 32 + nf * 8 + tg * 2;
#pragma unroll
            for (int half = 0; half < 2; half++) {
                int m = m0 + wm * 64 + mf * 16 + grp + half * 8;
                float2 v = make_float2(acc[mf][nf][half * 2], acc[mf][nf][half * 2 + 1]);
                if (SPLIT) {
                    int b_ = m >> 11, s_ = m & 2047;
                    int h_ = n >> 6,  hd = n & 63;
                    *(float2*)&C[((size_t)(b_ * HH + h_) * SS + s_) * HDD + hd] = v;
                } else {
                    *(float2*)&C[(size_t)m * DD + n] = v;
                }
            }
        }
    }
}

// ---------------------------------------------------------------------------
// FMA-pipe exp
// ---------------------------------------------------------------------------
__device__ __forceinline__ float fast_exp(float x) {
    float t = fmaxf(x * 1.4426950408889634f, -126.0f);
    int   i = __float2int_rn(t);
    float f = t - (float)i;
    float p = 1.3333558146428443e-3f;
    p = fmaf(p, f, 9.6181291076284771e-3f);
    p = fmaf(p, f, 5.5504108664821580e-2f);
    p = fmaf(p, f, 2.4022650695910072e-1f);
    p = fmaf(p, f, 6.9314718055994531e-1f);
    p = fmaf(p, f, 1.0f);
    return p * __int_as_float((i + 127) << 23);
}

// ---------------------------------------------------------------------------
// Tensor-core flash attention: block = (64 q rows, one bh); 4 warps.
// QK^T in 3-term tf32 split (fp32-accurate scores); PV single tf32.
// ---------------------------------------------------------------------------
__global__ void __launch_bounds__(128) attn_mma(const int* __restrict__ valid_lens,
                                                float* __restrict__ out) {
    extern __shared__ float smf[];
    float* Qs = smf;                   // 64 x ATS (raw f32)
    float* Ks = smf + 64 * ATS;        // 64 x ATS (raw f32)
    float* Vt = smf + 2 * 64 * ATS;    // 64(hd) x ATS(key), tf32-rounded
    float* Ps = smf + 3 * 64 * ATS;    // 64 x ATS, tf32-rounded

    const int qt = blockIdx.x;
    const int bh = blockIdx.y;
    const int b  = bh >> 4;
    const int h  = bh & 15;
    const int vlen = valid_lens[b];

    const float* q = g_q + (size_t)bh * (SS * HDD);
    const float* k = g_k + (size_t)bh * (SS * HDD);
    const float* v = g_v + (size_t)bh * (SS * HDD);

    const int tid  = threadIdx.x;
    const int lane = tid & 31;
    const int w    = tid >> 5;
    const int grp  = lane >> 2;
    const int tg   = lane & 3;

    // stage Q (64x64)
#pragma unroll
    for (int i = 0; i < 8; i++) {
        int idx = tid + i * 128;        // float4 units
        int row = idx >> 4, c4 = (idx & 15) << 2;
        *(float4*)&Qs[row * ATS + c4] =
            *(const float4*)&q[(size_t)(qt * 64 + row) * HDD + c4];
    }

    float m_i[2] = {-1e30f, -1e30f}, l_i[2] = {0.f, 0.f};
    float O[8][4];
#pragma unroll
    for (int nf = 0; nf < 8; nf++)
#pragma unroll
        for (int r = 0; r < 4; r++) O[nf][r] = 0.f;

    const uint32_t sQ = smem_u32(Qs), sK = smem_u32(Ks);
    const uint32_t sV = smem_u32(Vt), sP = smem_u32(Ps);
    const uint32_t aAddrQ = sQ + (uint32_t)((w * 16 + (lane & 15)) * ATS) * 4 + (lane >> 4) * 16;
    const uint32_t aAddrP = sP + (uint32_t)((w * 16 + (lane & 15)) * ATS) * 4 + (lane >> 4) * 16;
    const uint32_t bRow   = ((lane >> 4) & 1) * 8 + (lane & 7);
    const uint32_t bHalf  = ((lane >> 3) & 1) * 16;

    const int ntiles = (vlen + 63) >> 6;
    for (int kt = 0; kt < ntiles; kt++) {
        __syncthreads();
        // stage K (raw f32)
#pragma unroll
        for (int i = 0; i < 8; i++) {
            int idx = tid + i * 128;
            int row = idx >> 4, c4 = (idx & 15) << 2;
            *(float4*)&Ks[row * ATS + c4] =
                *(const float4*)&k[(size_t)(kt * 64 + row) * HDD + c4];
        }
        // stage V transposed + tf32-rounded
#pragma unroll
        for (int i = 0; i < 32; i++) {
            int idx = tid + i * 128;
            int key = idx >> 6, hd = idx & 63;
            Vt[hd * ATS + key] = tf32r(v[(size_t)(kt * 64 + key) * HDD + hd]);
        }
        __syncthreads();

        // ---- S = Q K^T (3-term tf32 split) ----
        float sacc[8][4];
#pragma unroll
        for (int nf = 0; nf < 8; nf++)
#pragma unroll
            for (int r = 0; r < 4; r++) sacc[nf][r] = 0.f;

#pragma unroll
        for (int k8 = 0; k8 < 8; k8++) {
            const uint32_t kb = k8 * 32;
            uint32_t aq[4], ah[4], al[4];
            ldsm4(aq[0], aq[1], aq[2], aq[3], aAddrQ + kb);
#pragma unroll
            for (int i = 0; i < 4; i++) {
                float f  = __uint_as_float(aq[i]);
                float fh = tf32r(f);
                ah[i] = __float_as_uint(fh);
                al[i] = __float_as_uint(tf32r(f - fh));
            }
            uint32_t bh_[8][2], bl_[8][2];
#pragma unroll
            for (int bb = 0; bb < 4; bb++) {
                uint32_t r0, r1, r2, r3;
                ldsm4(r0, r1, r2, r3, sK + (bb * 16 + bRow) * (ATS * 4) + bHalf + kb);
                float f0 = __uint_as_float(r0), f1 = __uint_as_float(r1);
                float f2 = __uint_as_float(r2), f3 = __uint_as_float(r3);
                float h0 = tf32r(f0), h1 = tf32r(f1), h2 = tf32r(f2), h3 = tf32r(f3);
                bh_[bb*2+0][0] = __float_as_uint(h0); bh_[bb*2+0][1] = __float_as_uint(h1);
                bh_[bb*2+1][0] = __float_as_uint(h2); bh_[bb*2+1][1] = __float_as_uint(h3);
                bl_[bb*2+0][0] = __float_as_uint(tf32r(f0 - h0));
                bl_[bb*2+0][1] = __float_as_uint(tf32r(f1 - h1));
                bl_[bb*2+1][0] = __float_as_uint(tf32r(f2 - h2));
                bl_[bb*2+1][1] = __float_as_uint(tf32r(f3 - h3));
            }
#pragma unroll
            for (int nf = 0; nf < 8; nf++) {
                mma_tf32(sacc[nf], ah, bh_[nf]);
                mma_tf32(sacc[nf], ah, bl_[nf]);
                mma_tf32(sacc[nf], al, bh_[nf]);
            }
        }

        // ---- scale + mask ----
        const int kbase = kt * 64;
#pragma unroll
        for (int nf = 0; nf < 8; nf++) {
            int cg = kbase + nf * 8 + 2 * tg;
            bool mk0 = cg >= vlen, mk1 = (cg + 1) >= vlen;
#pragma unroll
            for (int hh = 0; hh < 2; hh++) {
                sacc[nf][hh*2+0] = mk0 ? -1e30f : sacc[nf][hh*2+0] * 0.125f;
                sacc[nf][hh*2+1] = mk1 ? -1e30f : sacc[nf][hh*2+1] * 0.125f;
            }
        }

        // ---- online softmax on fragments ----
#pragma unroll
        for (int hh = 0; hh < 2; hh++) {
            float mx = -1e30f;
#pragma unroll
            for (int nf = 0; nf < 8; nf++)
                mx = fmaxf(mx, fmaxf(sacc[nf][hh*2], sacc[nf][hh*2+1]));
            mx = fmaxf(mx, __shfl_xor_sync(0xffffffffu, mx, 1));
            mx = fmaxf(mx, __shfl_xor_sync(0xffffffffu, mx, 2));
            float m_new = fmaxf(m_i[hh], mx);
            float scl = fast_exp(m_i[hh] - m_new);
            m_i[hh] = m_new;
            float ps = 0.f;
            int prow = w * 16 + grp + hh * 8;
#pragma unroll
            for (int nf = 0; nf < 8; nf++) {
                float p0 = fast_exp(sacc[nf][hh*2+0] - m_new);
                float p1 = fast_exp(sacc[nf][hh*2+1] - m_new);
                ps += p0 + p1;
                *(float2*)&Ps[prow * ATS + nf * 8 + 2 * tg] =
                    make_float2(tf32r(p0), tf32r(p1));
            }
            ps += __shfl_xor_sync(0xffffffffu, ps, 1);
            ps += __shfl_xor_sync(0xffffffffu, ps, 2);
            l_i[hh] = l_i[hh] * scl + ps;
#pragma unroll
            for (int nf = 0; nf < 8; nf++) {
                O[nf][hh*2+0] *= scl;
                O[nf][hh*2+1] *= scl;
            }
        }
        __syncwarp();

        // ---- O += P V ----
#pragma unroll
        for (int k8 = 0; k8 < 8; k8++) {
            const uint32_t kb = k8 * 32;
            uint32_t ap[4];
            ldsm4(ap[0], ap[1], ap[2], ap[3], aAddrP + kb);
            uint32_t bv[8][2];
#pragma unroll
            for (int bb = 0; bb < 4; bb++) {
                uint32_t r0, r1, r2, r3;
                ldsm4(r0, r1, r2, r3, sV + (bb * 16 + bRow) * (ATS * 4) + bHalf + kb);
                bv[bb*2+0][0] = r0; bv[bb*2+0][1] = r1;
                bv[bb*2+1][0] = r2; bv[bb*2+1][1] = r3;
            }
#pragma unroll
            for (int nf = 0; nf < 8; nf++)
                mma_tf32(O[nf], ap, bv[nf]);
        }
    }

    // ---- epilogue: out[b][s][h*64+hd] ----
#pragma unroll
    for (int hh = 0; hh < 2; hh++) {
        float inv = 1.f / l_i[hh];
        int srow = qt * 64 + w * 16 + grp + hh * 8;
#pragma unroll
        for (int nf = 0; nf < 8; nf++) {
            int hd = nf * 8 + 2 * tg;
            float2 val = make_float2(O[nf][hh*2+0] * inv, O[nf][hh*2+1] * inv);
            *(float2*)&out[((size_t)b * SS + srow) * DD + h * HDD + hd] = val;
        }
    }
}

// ---------------------------------------------------------------------------
extern "C" void kernel_launch(void* const* d_in, const int* in_sizes, int n_in,
                              void* d_out, int out_size) {
    (void)in_sizes; (void)n_in; (void)out_size;
    const float* queries    = (const float*)d_in[0];
    const float* keys       = (const float*)d_in[1];
    const float* values     = (const float*)d_in[2];
    const int*   valid_lens = (const int*)  d_in[3];
    const float* Wq         = (const float*)d_in[4];
    const float* Wk         = (const float*)d_in[5];
    const float* Wv         = (const float*)d_in[6];
    const float* Wo         = (const float*)d_in[7];
    float* out = (float*)d_out;

    float *pq, *pk, *pv, *pa, *pwt;
    cudaGetSymbolAddress((void**)&pq, g_q);
    cudaGetSymbolAddress((void**)&pk, g_k);
    cudaGetSymbolAddress((void**)&pv, g_v);
    cudaGetSymbolAddress((void**)&pa, g_attn);
    cudaGetSymbolAddress((void**)&pwt, g_wt);

    const int attn_smem = 4 * 64 * ATS * sizeof(float);   // 69632
    cudaFuncSetAttribute(attn_mma, cudaFuncAttributeMaxDynamicSharedMemorySize, attn_smem);

    dim3 tw_grid(32, 32), tw_blk(32, 32);
    dim3 gg(DD / 128, M_TOT / 128);
    dim3 gb(256);

    transpose_w<<<tw_grid, tw_blk>>>(Wq, pwt);
    gemm32<true><<<gg, gb>>>(queries, pwt, pq);
    transpose_w<<<tw_grid, tw_blk>>>(Wk, pwt);
    gemm32<true><<<gg, gb>>>(keys, pwt, pk);
    transpose_w<<<tw_grid, tw_blk>>>(Wv, pwt);
    gemm32<true><<<gg, gb>>>(values, pwt, pv);

    dim3 agrid(SS / 64, BB * HH);
    attn_mma<<<agrid, 128, attn_smem>>>(valid_lens, pa);

    transpose_w<<<tw_grid, tw_blk>>>(Wo, pwt);
    gemm32<false><<<gg, gb>>>(pa, pwt, out);
}

// round 7
// speedup vs baseline: 2.4800x; 1.1225x over previous
#include <cuda_runtime.h>
#include <math.h>
#include <stdint.h>

#define BB 4
#define SS 2048
#define DD 1024
#define HH 16
#define HDD 64
#define M_TOT (BB*SS)     // 8192
#define GKP 1024          // projection K
#define BK2 32            // k per chunk (gemm v2)
#define NCH2 (GKP/BK2)    // 32
#define STR2 36           // f32 per smem row (144B, conflict-free)
#define ATS 68            // f32 per smem row in attention (272B)

// ---------------------------------------------------------------------------
// scratch (__device__ globals; allocation-free)
// ---------------------------------------------------------------------------
__device__ float g_q[(size_t)BB*HH*SS*HDD];
__device__ float g_k[(size_t)BB*HH*SS*HDD];
__device__ float g_v[(size_t)BB*HH*SS*HDD];
__device__ float g_attn[(size_t)BB*SS*DD];
__device__ float g_wt[(size_t)DD*DD];     // transposed + tf32-rounded weight
__device__ float g_at[(size_t)M_TOT*GKP]; // tf32-rounded activation

// ---------------------------------------------------------------------------
// PTX helpers (baseline sm_80-level PTX only)
// ---------------------------------------------------------------------------
__device__ __forceinline__ uint32_t smem_u32(const void* p) {
    return (uint32_t)__cvta_generic_to_shared(p);
}
__device__ __forceinline__ void cp16(uint32_t dst, const void* src) {
    asm volatile("cp.async.cg.shared.global [%0], [%1], 16;" :: "r"(dst), "l"(src));
}
__device__ __forceinline__ void cp_commit() {
    asm volatile("cp.async.commit_group;" ::: "memory");
}
template<int N>
__device__ __forceinline__ void cp_wait() {
    asm volatile("cp.async.wait_group %0;" :: "n"(N) : "memory");
}
__device__ __forceinline__ void ldsm4(uint32_t& r0, uint32_t& r1, uint32_t& r2, uint32_t& r3,
                                      uint32_t addr) {
    asm volatile("ldmatrix.sync.aligned.m8n8.x4.shared.b16 {%0,%1,%2,%3}, [%4];"
                 : "=r"(r0), "=r"(r1), "=r"(r2), "=r"(r3) : "r"(addr));
}
__device__ __forceinline__ uint32_t to_tf32(uint32_t x) {
    uint32_t y;
    asm("cvt.rna.tf32.f32 %0, %1;" : "=r"(y) : "r"(x));
    return y;
}
__device__ __forceinline__ float tf32r(float x) {
    return __uint_as_float(to_tf32(__float_as_uint(x)));
}
__device__ __forceinline__ void mma_tf32(float* c, const uint32_t* a, const uint32_t* b) {
    asm volatile("mma.sync.aligned.m16n8k8.row.col.f32.tf32.tf32.f32 "
                 "{%0,%1,%2,%3}, {%4,%5,%6,%7}, {%8,%9}, {%0,%1,%2,%3};"
                 : "+f"(c[0]), "+f"(c[1]), "+f"(c[2]), "+f"(c[3])
                 : "r"(a[0]), "r"(a[1]), "r"(a[2]), "r"(a[3]), "r"(b[0]), "r"(b[1]));
}

// ---------------------------------------------------------------------------
// W [1024(k) x 1024(n)] -> WT [1024(n) x 1024(k)], tf32-rounded
// ---------------------------------------------------------------------------
__global__ void __launch_bounds__(1024) transpose_w(const float* __restrict__ W,
                                                    float* __restrict__ WT) {
    __shared__ float t[32][33];
    int k0 = blockIdx.y * 32, n0 = blockIdx.x * 32;
    t[threadIdx.y][threadIdx.x] = W[(size_t)(k0 + threadIdx.y) * 1024 + n0 + threadIdx.x];
    __syncthreads();
    WT[(size_t)(n0 + threadIdx.y) * 1024 + k0 + threadIdx.x] = tf32r(t[threadIdx.x][threadIdx.y]);
}

// A -> tf32-rounded copy
__global__ void __launch_bounds__(256) round_a(const float4* __restrict__ in,
                                               float4* __restrict__ out) {
    int idx = blockIdx.x * 256 + threadIdx.x;
    float4 v = in[idx];
    v.x = tf32r(v.x); v.y = tf32r(v.y); v.z = tf32r(v.z); v.w = tf32r(v.w);
    out[idx] = v;
}

// ---------------------------------------------------------------------------
// tf32 GEMM v2: operands pre-rounded; BK=32; no cvt in loop.
// C[m,n] = sum_k A[m,k]*B[n,k]; M=8192, N=1024, K=1024
// ---------------------------------------------------------------------------
template<bool SPLIT>
__global__ void __launch_bounds__(256, 2) gemm32(const float* __restrict__ A,
                                                 const float* __restrict__ B,
                                                 float* __restrict__ C) {
    extern __shared__ float smg[];
    // layout (floats): As0 @0, As1 @4608, Bs0 @9216, Bs1 @13824
    const uint32_t sbase = smem_u32(smg);

    const int tid  = threadIdx.x;
    const int lane = tid & 31;
    const int warp = tid >> 5;
    const int wm   = warp & 1;
    const int wn   = warp >> 1;
    const int m0   = blockIdx.y * 128;
    const int n0   = blockIdx.x * 128;

    const float* Arow = A + (size_t)m0 * GKP;
    const float* Brow = B + (size_t)n0 * GKP;

    auto load_chunk = [&](int buf, int c) {
        const size_t kof = (size_t)c * BK2;
        const uint32_t dA = sbase + (buf ? 4608u : 0u) * 4u;
        const uint32_t dB = sbase + (buf ? 13824u : 9216u) * 4u;
#pragma unroll
        for (int u = 0; u < 4; u++) {
            int task = tid + u * 256;       // 0..1023
            int row  = task >> 3;           // 0..127
            int seg  = task & 7;            // 16B segments
            uint32_t so = (uint32_t)(row * STR2 + seg * 4) * 4;
            cp16(dA + so, Arow + (size_t)row * GKP + kof + seg * 4);
            cp16(dB + so, Brow + (size_t)row * GKP + kof + seg * 4);
        }
        cp_commit();
    };

    float acc[4][4][4];
#pragma unroll
    for (int i = 0; i < 4; i++)
#pragma unroll
        for (int j = 0; j < 4; j++)
#pragma unroll
            for (int r = 0; r < 4; r++) acc[i][j][r] = 0.f;

    load_chunk(0, 0);

    for (int c = 0; c < NCH2; c++) {
        const int buf = c & 1;
        if (c + 1 < NCH2) {
            load_chunk(buf ^ 1, c + 1);
            cp_wait<1>();
        } else {
            cp_wait<0>();
        }
        __syncthreads();

        const uint32_t sA = sbase + (buf ? 4608u : 0u) * 4u;
        const uint32_t sB = sbase + (buf ? 13824u : 9216u) * 4u;
        const uint32_t aBase = sA + (uint32_t)((wm * 64 + (lane & 15)) * STR2) * 4
                             + (lane >> 4) * 16;
        const uint32_t bBase = sB + (uint32_t)((wn * 32 + ((lane >> 4) & 1) * 8 + (lane & 7)) * STR2) * 4
                             + ((lane >> 3) & 1) * 16;
#pragma unroll
        for (int k8 = 0; k8 < 4; k8++) {
            const uint32_t kb = k8 * 32;
            uint32_t a[4][4];
#pragma unroll
            for (int mf = 0; mf < 4; mf++)
                ldsm4(a[mf][0], a[mf][1], a[mf][2], a[mf][3],
                      aBase + (uint32_t)(mf * 16 * STR2) * 4 + kb);
            uint32_t b[4][2];
#pragma unroll
            for (int bb = 0; bb < 2; bb++) {
                uint32_t r0, r1, r2, r3;
                ldsm4(r0, r1, r2, r3, bBase + (uint32_t)(bb * 16 * STR2) * 4 + kb);
                b[bb * 2 + 0][0] = r0; b[bb * 2 + 0][1] = r1;
                b[bb * 2 + 1][0] = r2; b[bb * 2 + 1][1] = r3;
            }
#pragma unroll
            for (int mf = 0; mf < 4; mf++)
#pragma unroll
                for (int nf = 0; nf < 4; nf++)
                    mma_tf32(acc[mf][nf], a[mf], b[nf]);
        }
        __syncthreads();
    }

    const int grp = lane >> 2;
    const int tg  = lane & 3;
#pragma unroll
    for (int mf = 0; mf < 4; mf++) {
#pragma unroll
        for (int nf = 0; nf < 4; nf++) {
            int n = n0 + wn * 32 + nf * 8 + tg * 2;
#pragma unroll
            for (int half = 0; half < 2; half++) {
                int m = m0 + wm * 64 + mf * 16 + grp + half * 8;
                float2 v = make_float2(acc[mf][nf][half * 2], acc[mf][nf][half * 2 + 1]);
                if (SPLIT) {
                    int b_ = m >> 11, s_ = m & 2047;
                    int h_ = n >> 6,  hd = n & 63;
                    *(float2*)&C[((size_t)(b_ * HH + h_) * SS + s_) * HDD + hd] = v;
                } else {
                    *(float2*)&C[(size_t)m * DD + n] = v;
                }
            }
        }
    }
}

// ---------------------------------------------------------------------------
// FMA-pipe exp
// ---------------------------------------------------------------------------
__device__ __forceinline__ float fast_exp(float x) {
    float t = fmaxf(x * 1.4426950408889634f, -126.0f);
    int   i = __float2int_rn(t);
    float f = t - (float)i;
    float p = 1.3333558146428443e-3f;
    p = fmaf(p, f, 9.6181291076284771e-3f);
    p = fmaf(p, f, 5.5504108664821580e-2f);
    p = fmaf(p, f, 2.4022650695910072e-1f);
    p = fmaf(p, f, 6.9314718055994531e-1f);
    p = fmaf(p, f, 1.0f);
    return p * __int_as_float((i + 127) << 23);
}

// ---------------------------------------------------------------------------
// Tensor-core flash attention v2: hi/lo split staged in smem (computed once),
// pure ldsm+mma inner loops. 4 warps, 64 q rows per CTA.
// ---------------------------------------------------------------------------
#define AT (64*ATS)   // tile floats

__global__ void __launch_bounds__(128) attn_mma(const int* __restrict__ valid_lens,
                                                float* __restrict__ out) {
    extern __shared__ float smf[];
    float* Qh = smf;            // tf32 hi of Q
    float* Ql = smf + AT;       // tf32 lo of Q
    float* Kh = smf + 2*AT;
    float* Kl = smf + 3*AT;
    float* Vt = smf + 4*AT;     // V transposed, tf32-rounded
    float* Ps = smf + 5*AT;     // P, tf32-rounded

    const int qt = blockIdx.x;
    const int bh = blockIdx.y;
    const int b  = bh >> 4;
    const int h  = bh & 15;
    const int vlen = valid_lens[b];

    const float* q = g_q + (size_t)bh * (SS * HDD);
    const float* k = g_k + (size_t)bh * (SS * HDD);
    const float* v = g_v + (size_t)bh * (SS * HDD);

    const int tid  = threadIdx.x;
    const int lane = tid & 31;
    const int w    = tid >> 5;
    const int grp  = lane >> 2;
    const int tg   = lane & 3;

    // stage Q hi/lo (once per CTA)
#pragma unroll
    for (int i = 0; i < 8; i++) {
        int idx = tid + i * 128;
        int row = idx >> 4, c4 = (idx & 15) << 2;
        float4 t = *(const float4*)&q[(size_t)(qt * 64 + row) * HDD + c4];
        float4 hi, lo;
        hi.x = tf32r(t.x); lo.x = tf32r(t.x - hi.x);
        hi.y = tf32r(t.y); lo.y = tf32r(t.y - hi.y);
        hi.z = tf32r(t.z); lo.z = tf32r(t.z - hi.z);
        hi.w = tf32r(t.w); lo.w = tf32r(t.w - hi.w);
        *(float4*)&Qh[row * ATS + c4] = hi;
        *(float4*)&Ql[row * ATS + c4] = lo;
    }

    float m_i[2] = {-1e30f, -1e30f}, l_i[2] = {0.f, 0.f};
    float O[8][4];
#pragma unroll
    for (int nf = 0; nf < 8; nf++)
#pragma unroll
        for (int r = 0; r < 4; r++) O[nf][r] = 0.f;

    const uint32_t sQh = smem_u32(Qh), sQl = smem_u32(Ql);
    const uint32_t sKh = smem_u32(Kh), sKl = smem_u32(Kl);
    const uint32_t sV  = smem_u32(Vt), sP  = smem_u32(Ps);
    const uint32_t aOff  = (uint32_t)((w * 16 + (lane & 15)) * ATS) * 4 + (lane >> 4) * 16;
    const uint32_t bOff  = (uint32_t)((((lane >> 4) & 1) * 8 + (lane & 7)) * ATS) * 4
                         + ((lane >> 3) & 1) * 16;

    const int ntiles = (vlen + 63) >> 6;
    for (int kt = 0; kt < ntiles; kt++) {
        __syncthreads();
        // stage K hi/lo
#pragma unroll
        for (int i = 0; i < 8; i++) {
            int idx = tid + i * 128;
            int row = idx >> 4, c4 = (idx & 15) << 2;
            float4 t = *(const float4*)&k[(size_t)(kt * 64 + row) * HDD + c4];
            float4 hi, lo;
            hi.x = tf32r(t.x); lo.x = tf32r(t.x - hi.x);
            hi.y = tf32r(t.y); lo.y = tf32r(t.y - hi.y);
            hi.z = tf32r(t.z); lo.z = tf32r(t.z - hi.z);
            hi.w = tf32r(t.w); lo.w = tf32r(t.w - hi.w);
            *(float4*)&Kh[row * ATS + c4] = hi;
            *(float4*)&Kl[row * ATS + c4] = lo;
        }
        // stage V transposed + rounded
#pragma unroll
        for (int i = 0; i < 32; i++) {
            int idx = tid + i * 128;
            int key = idx >> 6, hd = idx & 63;
            Vt[hd * ATS + key] = tf32r(v[(size_t)(kt * 64 + key) * HDD + hd]);
        }
        __syncthreads();

        // ---- S = Q K^T (3-term split, pure ldsm+mma) ----
        float sacc[8][4];
#pragma unroll
        for (int nf = 0; nf < 8; nf++)
#pragma unroll
            for (int r = 0; r < 4; r++) sacc[nf][r] = 0.f;

#pragma unroll
        for (int k8 = 0; k8 < 8; k8++) {
            const uint32_t kb = k8 * 32;
            uint32_t qh[4], ql[4];
            ldsm4(qh[0], qh[1], qh[2], qh[3], sQh + aOff + kb);
            ldsm4(ql[0], ql[1], ql[2], ql[3], sQl + aOff + kb);
#pragma unroll
            for (int bbq = 0; bbq < 4; bbq++) {
                const uint32_t ro = (uint32_t)(bbq * 16 * ATS) * 4;
                uint32_t kh[4], kl[4];
                ldsm4(kh[0], kh[1], kh[2], kh[3], sKh + bOff + ro + kb);
                ldsm4(kl[0], kl[1], kl[2], kl[3], sKl + bOff + ro + kb);
                mma_tf32(sacc[bbq*2+0], qh, &kh[0]);
                mma_tf32(sacc[bbq*2+0], qh, &kl[0]);
                mma_tf32(sacc[bbq*2+0], ql, &kh[0]);
                mma_tf32(sacc[bbq*2+1], qh, &kh[2]);
                mma_tf32(sacc[bbq*2+1], qh, &kl[2]);
                mma_tf32(sacc[bbq*2+1], ql, &kh[2]);
            }
        }

        // ---- scale + mask ----
        const int kbase = kt * 64;
#pragma unroll
        for (int nf = 0; nf < 8; nf++) {
            int cg = kbase + nf * 8 + 2 * tg;
            bool mk0 = cg >= vlen, mk1 = (cg + 1) >= vlen;
#pragma unroll
            for (int hh = 0; hh < 2; hh++) {
                sacc[nf][hh*2+0] = mk0 ? -1e30f : sacc[nf][hh*2+0] * 0.125f;
                sacc[nf][hh*2+1] = mk1 ? -1e30f : sacc[nf][hh*2+1] * 0.125f;
            }
        }

        // ---- online softmax on fragments ----
#pragma unroll
        for (int hh = 0; hh < 2; hh++) {
            float mx = -1e30f;
#pragma unroll
            for (int nf = 0; nf < 8; nf++)
                mx = fmaxf(mx, fmaxf(sacc[nf][hh*2], sacc[nf][hh*2+1]));
            mx = fmaxf(mx, __shfl_xor_sync(0xffffffffu, mx, 1));
            mx = fmaxf(mx, __shfl_xor_sync(0xffffffffu, mx, 2));
            float m_new = fmaxf(m_i[hh], mx);
            float scl = fast_exp(m_i[hh] - m_new);
            m_i[hh] = m_new;
            float ps = 0.f;
            int prow = w * 16 + grp + hh * 8;
#pragma unroll
            for (int nf = 0; nf < 8; nf++) {
                float p0 = fast_exp(sacc[nf][hh*2+0] - m_new);
                float p1 = fast_exp(sacc[nf][hh*2+1] - m_new);
                ps += p0 + p1;
                *(float2*)&Ps[prow * ATS + nf * 8 + 2 * tg] =
                    make_float2(tf32r(p0), tf32r(p1));
            }
            ps += __shfl_xor_sync(0xffffffffu, ps, 1);
            ps += __shfl_xor_sync(0xffffffffu, ps, 2);
            l_i[hh] = l_i[hh] * scl + ps;
#pragma unroll
            for (int nf = 0; nf < 8; nf++) {
                O[nf][hh*2+0] *= scl;
                O[nf][hh*2+1] *= scl;
            }
        }
        __syncwarp();

        // ---- O += P V ----
#pragma unroll
        for (int k8 = 0; k8 < 8; k8++) {
            const uint32_t kb = k8 * 32;
            uint32_t ap[4];
            ldsm4(ap[0], ap[1], ap[2], ap[3], sP + aOff + kb);
#pragma unroll
            for (int bbv = 0; bbv < 4; bbv++) {
                uint32_t r0, r1, r2, r3;
                ldsm4(r0, r1, r2, r3, sV + bOff + (uint32_t)(bbv * 16 * ATS) * 4 + kb);
                uint32_t b0[2] = {r0, r1}, b1[2] = {r2, r3};
                mma_tf32(O[bbv*2+0], ap, b0);
                mma_tf32(O[bbv*2+1], ap, b1);
            }
        }
    }

    // ---- epilogue: rounded output (feeds pre-rounded Wo GEMM) ----
#pragma unroll
    for (int hh = 0; hh < 2; hh++) {
        float inv = 1.f / l_i[hh];
        int srow = qt * 64 + w * 16 + grp + hh * 8;
#pragma unroll
        for (int nf = 0; nf < 8; nf++) {
            int hd = nf * 8 + 2 * tg;
            float2 val = make_float2(tf32r(O[nf][hh*2+0] * inv), tf32r(O[nf][hh*2+1] * inv));
            *(float2*)&out[((size_t)b * SS + srow) * DD + h * HDD + hd] = val;
        }
    }
}

// ---------------------------------------------------------------------------
extern "C" void kernel_launch(void* const* d_in, const int* in_sizes, int n_in,
                              void* d_out, int out_size) {
    (void)in_sizes; (void)n_in; (void)out_size;
    const float* queries    = (const float*)d_in[0];
    const float* keys       = (const float*)d_in[1];
    const float* values     = (const float*)d_in[2];
    const int*   valid_lens = (const int*)  d_in[3];
    const float* Wq         = (const float*)d_in[4];
    const float* Wk         = (const float*)d_in[5];
    const float* Wv         = (const float*)d_in[6];
    const float* Wo         = (const float*)d_in[7];
    float* out = (float*)d_out;

    float *pq, *pk, *pv, *pa, *pwt, *pat;
    cudaGetSymbolAddress((void**)&pq, g_q);
    cudaGetSymbolAddress((void**)&pk, g_k);
    cudaGetSymbolAddress((void**)&pv, g_v);
    cudaGetSymbolAddress((void**)&pa, g_attn);
    cudaGetSymbolAddress((void**)&pwt, g_wt);
    cudaGetSymbolAddress((void**)&pat, g_at);

    const int gemm_smem = 4 * 128 * STR2 * sizeof(float);     // 73728
    cudaFuncSetAttribute(gemm32<true>,  cudaFuncAttributeMaxDynamicSharedMemorySize, gemm_smem);
    cudaFuncSetAttribute(gemm32<false>, cudaFuncAttributeMaxDynamicSharedMemorySize, gemm_smem);
    const int attn_smem = 6 * AT * sizeof(float);             // 104448
    cudaFuncSetAttribute(attn_mma, cudaFuncAttributeMaxDynamicSharedMemorySize, attn_smem);

    dim3 tw_grid(32, 32), tw_blk(32, 32);
    dim3 ra_grid(M_TOT * GKP / 4 / 256);
    dim3 gg(DD / 128, M_TOT / 128);
    dim3 gb(256);

    transpose_w<<<tw_grid, tw_blk>>>(Wq, pwt);
    round_a<<<ra_grid, 256>>>((const float4*)queries, (float4*)pat);
    gemm32<true><<<gg, gb, gemm_smem>>>(pat, pwt, pq);

    transpose_w<<<tw_grid, tw_blk>>>(Wk, pwt);
    round_a<<<ra_grid, 256>>>((const float4*)keys, (float4*)pat);
    gemm32<true><<<gg, gb, gemm_smem>>>(pat, pwt, pk);

    transpose_w<<<tw_grid, tw_blk>>>(Wv, pwt);
    round_a<<<ra_grid, 256>>>((const float4*)values, (float4*)pat);
    gemm32<true><<<gg, gb, gemm_smem>>>(pat, pwt, pv);

    dim3 agrid(SS / 64, BB * HH);
    attn_mma<<<agrid, 128, attn_smem>>>(valid_lens, pa);

    transpose_w<<<tw_grid, tw_blk>>>(Wo, pwt);
    gemm32<false><<<gg, gb, gemm_smem>>>(pa, pwt, out);
}

// round 8
// speedup vs baseline: 2.5681x; 1.0355x over previous
#include <cuda_runtime.h>
#include <math.h>
#include <stdint.h>

#define BB 4
#define SS 2048
#define DD 1024
#define HH 16
#define HDD 64
#define M_TOT (BB*SS)     // 8192
#define GKP 1024          // projection K
#define BK2 32            // k per chunk (gemm)
#define NCH2 (GKP/BK2)    // 32
#define STR2 36           // f32 per smem row (144B)
#define ATS 68            // f32 per smem row in attention (272B)
#define AT (64*ATS)

// ---------------------------------------------------------------------------
// scratch (__device__ globals; allocation-free)
// ---------------------------------------------------------------------------
__device__ float g_q[(size_t)BB*HH*SS*HDD];
__device__ float g_k[(size_t)BB*HH*SS*HDD];   // tf32-rounded at projection
__device__ float g_v[(size_t)BB*HH*SS*HDD];   // tf32-rounded at projection
__device__ float g_attn[(size_t)BB*SS*DD];    // tf32-rounded at attn epilogue
__device__ float g_wt[(size_t)DD*DD];         // transposed + tf32-rounded weight
__device__ float g_at[(size_t)M_TOT*GKP];     // tf32-rounded activation

// ---------------------------------------------------------------------------
// PTX helpers (baseline sm_80-level PTX only)
// ---------------------------------------------------------------------------
__device__ __forceinline__ uint32_t smem_u32(const void* p) {
    return (uint32_t)__cvta_generic_to_shared(p);
}
__device__ __forceinline__ void cp16(uint32_t dst, const void* src) {
    asm volatile("cp.async.cg.shared.global [%0], [%1], 16;" :: "r"(dst), "l"(src));
}
__device__ __forceinline__ void cp_commit() {
    asm volatile("cp.async.commit_group;" ::: "memory");
}
template<int N>
__device__ __forceinline__ void cp_wait() {
    asm volatile("cp.async.wait_group %0;" :: "n"(N) : "memory");
}
__device__ __forceinline__ void ldsm4(uint32_t& r0, uint32_t& r1, uint32_t& r2, uint32_t& r3,
                                      uint32_t addr) {
    asm volatile("ldmatrix.sync.aligned.m8n8.x4.shared.b16 {%0,%1,%2,%3}, [%4];"
                 : "=r"(r0), "=r"(r1), "=r"(r2), "=r"(r3) : "r"(addr));
}
__device__ __forceinline__ uint32_t to_tf32(uint32_t x) {
    uint32_t y;
    asm("cvt.rna.tf32.f32 %0, %1;" : "=r"(y) : "r"(x));
    return y;
}
__device__ __forceinline__ float tf32r(float x) {
    return __uint_as_float(to_tf32(__float_as_uint(x)));
}
__device__ __forceinline__ void mma_tf32(float* c, const uint32_t* a, const uint32_t* b) {
    asm volatile("mma.sync.aligned.m16n8k8.row.col.f32.tf32.tf32.f32 "
                 "{%0,%1,%2,%3}, {%4,%5,%6,%7}, {%8,%9}, {%0,%1,%2,%3};"
                 : "+f"(c[0]), "+f"(c[1]), "+f"(c[2]), "+f"(c[3])
                 : "r"(a[0]), "r"(a[1]), "r"(a[2]), "r"(a[3]), "r"(b[0]), "r"(b[1]));
}

// ---------------------------------------------------------------------------
__global__ void __launch_bounds__(1024) transpose_w(const float* __restrict__ W,
                                                    float* __restrict__ WT) {
    __shared__ float t[32][33];
    int k0 = blockIdx.y * 32, n0 = blockIdx.x * 32;
    t[threadIdx.y][threadIdx.x] = W[(size_t)(k0 + threadIdx.y) * 1024 + n0 + threadIdx.x];
    __syncthreads();
    WT[(size_t)(n0 + threadIdx.y) * 1024 + k0 + threadIdx.x] = tf32r(t[threadIdx.x][threadIdx.y]);
}

__global__ void __launch_bounds__(256) round_a(const float4* __restrict__ in,
                                               float4* __restrict__ out) {
    int idx = blockIdx.x * 256 + threadIdx.x;
    float4 v = in[idx];
    v.x = tf32r(v.x); v.y = tf32r(v.y); v.z = tf32r(v.z); v.w = tf32r(v.w);
    out[idx] = v;
}

// ---------------------------------------------------------------------------
// tf32 GEMM: operands pre-rounded; BK=32; no cvt in loop.
// OMODE: 0 = plain row-major out; 1 = head-split out; 2 = head-split + tf32-rounded out
// ---------------------------------------------------------------------------
template<int OMODE>
__global__ void __launch_bounds__(256, 2) gemm32(const float* __restrict__ A,
                                                 const float* __restrict__ B,
                                                 float* __restrict__ C) {
    extern __shared__ float smg[];
    const uint32_t sbase = smem_u32(smg);

    const int tid  = threadIdx.x;
    const int lane = tid & 31;
    const int warp = tid >> 5;
    const int wm   = warp & 1;
    const int wn   = warp >> 1;
    const int m0   = blockIdx.y * 128;
    const int n0   = blockIdx.x * 128;

    const float* Arow = A + (size_t)m0 * GKP;
    const float* Brow = B + (size_t)n0 * GKP;

    auto load_chunk = [&](int buf, int c) {
        const size_t kof = (size_t)c * BK2;
        const uint32_t dA = sbase + (buf ? 4608u : 0u) * 4u;
        const uint32_t dB = sbase + (buf ? 13824u : 9216u) * 4u;
#pragma unroll
        for (int u = 0; u < 4; u++) {
            int task = tid + u * 256;
            int row  = task >> 3;
            int seg  = task & 7;
            uint32_t so = (uint32_t)(row * STR2 + seg * 4) * 4;
            cp16(dA + so, Arow + (size_t)row * GKP + kof + seg * 4);
            cp16(dB + so, Brow + (size_t)row * GKP + kof + seg * 4);
        }
        cp_commit();
    };

    float acc[4][4][4];
#pragma unroll
    for (int i = 0; i < 4; i++)
#pragma unroll
        for (int j = 0; j < 4; j++)
#pragma unroll
            for (int r = 0; r < 4; r++) acc[i][j][r] = 0.f;

    load_chunk(0, 0);

    for (int c = 0; c < NCH2; c++) {
        const int buf = c & 1;
        if (c + 1 < NCH2) {
            load_chunk(buf ^ 1, c + 1);
            cp_wait<1>();
        } else {
            cp_wait<0>();
        }
        __syncthreads();

        const uint32_t sA = sbase + (buf ? 4608u : 0u) * 4u;
        const uint32_t sB = sbase + (buf ? 13824u : 9216u) * 4u;
        const uint32_t aBase = sA + (uint32_t)((wm * 64 + (lane & 15)) * STR2) * 4
                             + (lane >> 4) * 16;
        const uint32_t bBase = sB + (uint32_t)((wn * 32 + ((lane >> 4) & 1) * 8 + (lane & 7)) * STR2) * 4
                             + ((lane >> 3) & 1) * 16;
#pragma unroll
        for (int k8 = 0; k8 < 4; k8++) {
            const uint32_t kb = k8 * 32;
            uint32_t a[4][4];
#pragma unroll
            for (int mf = 0; mf < 4; mf++)
                ldsm4(a[mf][0], a[mf][1], a[mf][2], a[mf][3],
                      aBase + (uint32_t)(mf * 16 * STR2) * 4 + kb);
            uint32_t b[4][2];
#pragma unroll
            for (int bb = 0; bb < 2; bb++) {
                uint32_t r0, r1, r2, r3;
                ldsm4(r0, r1, r2, r3, bBase + (uint32_t)(bb * 16 * STR2) * 4 + kb);
                b[bb * 2 + 0][0] = r0; b[bb * 2 + 0][1] = r1;
                b[bb * 2 + 1][0] = r2; b[bb * 2 + 1][1] = r3;
            }
#pragma unroll
            for (int mf = 0; mf < 4; mf++)
#pragma unroll
                for (int nf = 0; nf < 4; nf++)
                    mma_tf32(acc[mf][nf], a[mf], b[nf]);
        }
        __syncthreads();
    }

    const int grp = lane >> 2;
    const int tg  = lane & 3;
#pragma unroll
    for (int mf = 0; mf < 4; mf++) {
#pragma unroll
        for (int nf = 0; nf < 4; nf++) {
            int n = n0 + wn * 32 + nf * 8 + tg * 2;
#pragma unroll
            for (int half = 0; half < 2; half++) {
                int m = m0 + wm * 64 + mf * 16 + grp + half * 8;
                float2 v = make_float2(acc[mf][nf][half * 2], acc[mf][nf][half * 2 + 1]);
                if (OMODE == 2) { v.x = tf32r(v.x); v.y = tf32r(v.y); }
                if (OMODE >= 1) {
                    int b_ = m >> 11, s_ = m & 2047;
                    int h_ = n >> 6,  hd = n & 63;
                    *(float2*)&C[((size_t)(b_ * HH + h_) * SS + s_) * HDD + hd] = v;
                } else {
                    *(float2*)&C[(size_t)m * DD + n] = v;
                }
            }
        }
    }
}

// ---------------------------------------------------------------------------
__device__ __forceinline__ float fast_exp(float x) {
    float t = fmaxf(x * 1.4426950408889634f, -126.0f);
    int   i = __float2int_rn(t);
    float f = t - (float)i;
    float p = 1.3333558146428443e-3f;
    p = fmaf(p, f, 9.6181291076284771e-3f);
    p = fmaf(p, f, 5.5504108664821580e-2f);
    p = fmaf(p, f, 2.4022650695910072e-1f);
    p = fmaf(p, f, 6.9314718055994531e-1f);
    p = fmaf(p, f, 1.0f);
    return p * __int_as_float((i + 127) << 23);
}

// ---------------------------------------------------------------------------
// Tensor-core flash attention v3: S = qh*kh + ql*kh (K pre-rounded at source);
// K stage = pure copy, V stage = pure transpose. 4 warps, 64 q rows per CTA.
// ---------------------------------------------------------------------------
__global__ void __launch_bounds__(128) attn_mma(const int* __restrict__ valid_lens,
                                                float* __restrict__ out) {
    extern __shared__ float smf[];
    float* Qh = smf;            // tf32 hi of Q
    float* Ql = smf + AT;       // tf32 lo of Q
    float* Kh = smf + 2*AT;     // K (pre-rounded)
    float* Vt = smf + 3*AT;     // V transposed (pre-rounded)
    float* Ps = smf + 4*AT;     // P, tf32-rounded

    const int qt = blockIdx.x;
    const int bh = blockIdx.y;
    const int b  = bh >> 4;
    const int h  = bh & 15;
    const int vlen = valid_lens[b];

    const float* q = g_q + (size_t)bh * (SS * HDD);
    const float* k = g_k + (size_t)bh * (SS * HDD);
    const float* v = g_v + (size_t)bh * (SS * HDD);

    const int tid  = threadIdx.x;
    const int lane = tid & 31;
    const int w    = tid >> 5;
    const int grp  = lane >> 2;
    const int tg   = lane & 3;

    // stage Q hi/lo once
#pragma unroll
    for (int i = 0; i < 8; i++) {
        int idx = tid + i * 128;
        int row = idx >> 4, c4 = (idx & 15) << 2;
        float4 t = *(const float4*)&q[(size_t)(qt * 64 + row) * HDD + c4];
        float4 hi, lo;
        hi.x = tf32r(t.x); lo.x = tf32r(t.x - hi.x);
        hi.y = tf32r(t.y); lo.y = tf32r(t.y - hi.y);
        hi.z = tf32r(t.z); lo.z = tf32r(t.z - hi.z);
        hi.w = tf32r(t.w); lo.w = tf32r(t.w - hi.w);
        *(float4*)&Qh[row * ATS + c4] = hi;
        *(float4*)&Ql[row * ATS + c4] = lo;
    }

    float m_i[2] = {-1e30f, -1e30f}, l_i[2] = {0.f, 0.f};
    float O[8][4];
#pragma unroll
    for (int nf = 0; nf < 8; nf++)
#pragma unroll
        for (int r = 0; r < 4; r++) O[nf][r] = 0.f;

    const uint32_t sQh = smem_u32(Qh), sQl = smem_u32(Ql);
    const uint32_t sKh = smem_u32(Kh);
    const uint32_t sV  = smem_u32(Vt), sP  = smem_u32(Ps);
    const uint32_t aOff = (uint32_t)((w * 16 + (lane & 15)) * ATS) * 4 + (lane >> 4) * 16;
    const uint32_t bOff = (uint32_t)((((lane >> 4) & 1) * 8 + (lane & 7)) * ATS) * 4
                        + ((lane >> 3) & 1) * 16;

    const int ntiles = (vlen + 63) >> 6;
    for (int kt = 0; kt < ntiles; kt++) {
        __syncthreads();
        // stage K (plain copy; already tf32-rounded)
#pragma unroll
        for (int i = 0; i < 8; i++) {
            int idx = tid + i * 128;
            int row = idx >> 4, c4 = (idx & 15) << 2;
            *(float4*)&Kh[row * ATS + c4] =
                *(const float4*)&k[(size_t)(kt * 64 + row) * HDD + c4];
        }
        // stage V transposed (already rounded)
#pragma unroll
        for (int i = 0; i < 32; i++) {
            int idx = tid + i * 128;
            int key = idx >> 6, hd = idx & 63;
            Vt[hd * ATS + key] = v[(size_t)(kt * 64 + key) * HDD + hd];
        }
        __syncthreads();

        // ---- S = Qh K^T + Ql K^T ----
        float sacc[8][4];
#pragma unroll
        for (int nf = 0; nf < 8; nf++)
#pragma unroll
            for (int r = 0; r < 4; r++) sacc[nf][r] = 0.f;

#pragma unroll
        for (int k8 = 0; k8 < 8; k8++) {
            const uint32_t kb = k8 * 32;
            uint32_t qh[4], ql[4];
            ldsm4(qh[0], qh[1], qh[2], qh[3], sQh + aOff + kb);
            ldsm4(ql[0], ql[1], ql[2], ql[3], sQl + aOff + kb);
#pragma unroll
            for (int bbq = 0; bbq < 4; bbq++) {
                const uint32_t ro = (uint32_t)(bbq * 16 * ATS) * 4;
                uint32_t kh[4];
                ldsm4(kh[0], kh[1], kh[2], kh[3], sKh + bOff + ro + kb);
                mma_tf32(sacc[bbq*2+0], qh, &kh[0]);
                mma_tf32(sacc[bbq*2+0], ql, &kh[0]);
                mma_tf32(sacc[bbq*2+1], qh, &kh[2]);
                mma_tf32(sacc[bbq*2+1], ql, &kh[2]);
            }
        }

        // ---- scale + mask ----
        const int kbase = kt * 64;
#pragma unroll
        for (int nf = 0; nf < 8; nf++) {
            int cg = kbase + nf * 8 + 2 * tg;
            bool mk0 = cg >= vlen, mk1 = (cg + 1) >= vlen;
#pragma unroll
            for (int hh = 0; hh < 2; hh++) {
                sacc[nf][hh*2+0] = mk0 ? -1e30f : sacc[nf][hh*2+0] * 0.125f;
                sacc[nf][hh*2+1] = mk1 ? -1e30f : sacc[nf][hh*2+1] * 0.125f;
            }
        }

        // ---- online softmax ----
#pragma unroll
        for (int hh = 0; hh < 2; hh++) {
            float mx = -1e30f;
#pragma unroll
            for (int nf = 0; nf < 8; nf++)
                mx = fmaxf(mx, fmaxf(sacc[nf][hh*2], sacc[nf][hh*2+1]));
            mx = fmaxf(mx, __shfl_xor_sync(0xffffffffu, mx, 1));
            mx = fmaxf(mx, __shfl_xor_sync(0xffffffffu, mx, 2));
            float m_new = fmaxf(m_i[hh], mx);
            float scl = fast_exp(m_i[hh] - m_new);
            m_i[hh] = m_new;
            float ps = 0.f;
            int prow = w * 16 + grp + hh * 8;
#pragma unroll
            for (int nf = 0; nf < 8; nf++) {
                float p0 = fast_exp(sacc[nf][hh*2+0] - m_new);
                float p1 = fast_exp(sacc[nf][hh*2+1] - m_new);
                ps += p0 + p1;
                *(float2*)&Ps[prow * ATS + nf * 8 + 2 * tg] =
                    make_float2(tf32r(p0), tf32r(p1));
            }
            ps += __shfl_xor_sync(0xffffffffu, ps, 1);
            ps += __shfl_xor_sync(0xffffffffu, ps, 2);
            l_i[hh] = l_i[hh] * scl + ps;
#pragma unroll
            for (int nf = 0; nf < 8; nf++) {
                O[nf][hh*2+0] *= scl;
                O[nf][hh*2+1] *= scl;
            }
        }
        __syncwarp();

        // ---- O += P V ----
#pragma unroll
        for (int k8 = 0; k8 < 8; k8++) {
            const uint32_t kb = k8 * 32;
            uint32_t ap[4];
            ldsm4(ap[0], ap[1], ap[2], ap[3], sP + aOff + kb);
#pragma unroll
            for (int bbv = 0; bbv < 4; bbv++) {
                uint32_t r0, r1, r2, r3;
                ldsm4(r0, r1, r2, r3, sV + bOff + (uint32_t)(bbv * 16 * ATS) * 4 + kb);
                uint32_t b0[2] = {r0, r1}, b1[2] = {r2, r3};
                mma_tf32(O[bbv*2+0], ap, b0);
                mma_tf32(O[bbv*2+1], ap, b1);
            }
        }
    }

    // ---- epilogue (tf32-rounded; feeds Wo GEMM) ----
#pragma unroll
    for (int hh = 0; hh < 2; hh++) {
        float inv = 1.f / l_i[hh];
        int srow = qt * 64 + w * 16 + grp + hh * 8;
#pragma unroll
        for (int nf = 0; nf < 8; nf++) {
            int hd = nf * 8 + 2 * tg;
            float2 val = make_float2(tf32r(O[nf][hh*2+0] * inv), tf32r(O[nf][hh*2+1] * inv));
            *(float2*)&out[((size_t)b * SS + srow) * DD + h * HDD + hd] = val;
        }
    }
}

// ---------------------------------------------------------------------------
extern "C" void kernel_launch(void* const* d_in, const int* in_sizes, int n_in,
                              void* d_out, int out_size) {
    (void)in_sizes; (void)n_in; (void)out_size;
    const float* queries    = (const float*)d_in[0];
    const float* keys       = (const float*)d_in[1];
    const float* values     = (const float*)d_in[2];
    const int*   valid_lens = (const int*)  d_in[3];
    const float* Wq         = (const float*)d_in[4];
    const float* Wk         = (const float*)d_in[5];
    const float* Wv         = (const float*)d_in[6];
    const float* Wo         = (const float*)d_in[7];
    float* out = (float*)d_out;

    float *pq, *pk, *pv, *pa, *pwt, *pat;
    cudaGetSymbolAddress((void**)&pq, g_q);
    cudaGetSymbolAddress((void**)&pk, g_k);
    cudaGetSymbolAddress((void**)&pv, g_v);
    cudaGetSymbolAddress((void**)&pa, g_attn);
    cudaGetSymbolAddress((void**)&pwt, g_wt);
    cudaGetSymbolAddress((void**)&pat, g_at);

    const int gemm_smem = 4 * 128 * STR2 * sizeof(float);     // 73728
    cudaFuncSetAttribute(gemm32<0>, cudaFuncAttributeMaxDynamicSharedMemorySize, gemm_smem);
    cudaFuncSetAttribute(gemm32<1>, cudaFuncAttributeMaxDynamicSharedMemorySize, gemm_smem);
    cudaFuncSetAttribute(gemm32<2>, cudaFuncAttributeMaxDynamicSharedMemorySize, gemm_smem);
    const int attn_smem = 5 * AT * sizeof(float);             // 87040
    cudaFuncSetAttribute(attn_mma, cudaFuncAttributeMaxDynamicSharedMemorySize, attn_smem);

    dim3 tw_grid(32, 32), tw_blk(32, 32);
    dim3 ra_grid(M_TOT * GKP / 4 / 256);
    dim3 gg(DD / 128, M_TOT / 128);
    dim3 gb(256);

    transpose_w<<<tw_grid, tw_blk>>>(Wq, pwt);
    round_a<<<ra_grid, 256>>>((const float4*)queries, (float4*)pat);
    gemm32<1><<<gg, gb, gemm_smem>>>(pat, pwt, pq);

    transpose_w<<<tw_grid, tw_blk>>>(Wk, pwt);
    round_a<<<ra_grid, 256>>>((const float4*)keys, (float4*)pat);
    gemm32<2><<<gg, gb, gemm_smem>>>(pat, pwt, pk);

    transpose_w<<<tw_grid, tw_blk>>>(Wv, pwt);
    round_a<<<ra_grid, 256>>>((const float4*)values, (float4*)pat);
    gemm32<2><<<gg, gb, gemm_smem>>>(pat, pwt, pv);

    dim3 agrid(SS / 64, BB * HH);
    attn_mma<<<agrid, 128, attn_smem>>>(valid_lens, pa);

    transpose_w<<<tw_grid, tw_blk>>>(Wo, pwt);
    gemm32<0><<<gg, gb, gemm_smem>>>(pa, pwt, out);
}

// round 9
// speedup vs baseline: 2.6177x; 1.0193x over previous
#include <cuda_runtime.h>
#include <math.h>
#include <stdint.h>

#define BB 4
#define SS 2048
#define DD 1024
#define HH 16
#define HDD 64
#define M_TOT (BB*SS)     // 8192
#define GKP 1024          // projection K
#define BK2 32            // k per chunk (gemm)
#define NCH2 (GKP/BK2)    // 32
#define STR2 36           // f32 per smem row (144B)
#define ATS 68            // f32 per smem row in attention (272B)

// ---------------------------------------------------------------------------
// scratch (__device__ globals; allocation-free)
// ---------------------------------------------------------------------------
__device__ float g_q[(size_t)BB*HH*SS*HDD];
__device__ float g_k[(size_t)BB*HH*SS*HDD];   // tf32-rounded at projection
__device__ float g_v[(size_t)BB*HH*SS*HDD];   // tf32-rounded at projection
__device__ float g_attn[(size_t)BB*SS*DD];    // tf32-rounded at attn epilogue
__device__ float g_wt[(size_t)DD*DD];         // transposed + tf32-rounded weight
__device__ float g_at[(size_t)M_TOT*GKP];     // tf32-rounded activation

// ---------------------------------------------------------------------------
// PTX helpers (baseline sm_80-level PTX only)
// ---------------------------------------------------------------------------
__device__ __forceinline__ uint32_t smem_u32(const void* p) {
    return (uint32_t)__cvta_generic_to_shared(p);
}
__device__ __forceinline__ void cp16(uint32_t dst, const void* src) {
    asm volatile("cp.async.cg.shared.global [%0], [%1], 16;" :: "r"(dst), "l"(src));
}
__device__ __forceinline__ void cp_commit() {
    asm volatile("cp.async.commit_group;" ::: "memory");
}
template<int N>
__device__ __forceinline__ void cp_wait() {
    asm volatile("cp.async.wait_group %0;" :: "n"(N) : "memory");
}
__device__ __forceinline__ void ldsm4(uint32_t& r0, uint32_t& r1, uint32_t& r2, uint32_t& r3,
                                      uint32_t addr) {
    asm volatile("ldmatrix.sync.aligned.m8n8.x4.shared.b16 {%0,%1,%2,%3}, [%4];"
                 : "=r"(r0), "=r"(r1), "=r"(r2), "=r"(r3) : "r"(addr));
}
__device__ __forceinline__ uint32_t to_tf32(uint32_t x) {
    uint32_t y;
    asm("cvt.rna.tf32.f32 %0, %1;" : "=r"(y) : "r"(x));
    return y;
}
__device__ __forceinline__ float tf32r(float x) {
    return __uint_as_float(to_tf32(__float_as_uint(x)));
}
__device__ __forceinline__ void mma_tf32(float* c, const uint32_t* a, const uint32_t* b) {
    asm volatile("mma.sync.aligned.m16n8k8.row.col.f32.tf32.tf32.f32 "
                 "{%0,%1,%2,%3}, {%4,%5,%6,%7}, {%8,%9}, {%0,%1,%2,%3};"
                 : "+f"(c[0]), "+f"(c[1]), "+f"(c[2]), "+f"(c[3])
                 : "r"(a[0]), "r"(a[1]), "r"(a[2]), "r"(a[3]), "r"(b[0]), "r"(b[1]));
}

// ---------------------------------------------------------------------------
__global__ void __launch_bounds__(1024) transpose_w(const float* __restrict__ W,
                                                    float* __restrict__ WT) {
    __shared__ float t[32][33];
    int k0 = blockIdx.y * 32, n0 = blockIdx.x * 32;
    t[threadIdx.y][threadIdx.x] = W[(size_t)(k0 + threadIdx.y) * 1024 + n0 + threadIdx.x];
    __syncthreads();
    WT[(size_t)(n0 + threadIdx.y) * 1024 + k0 + threadIdx.x] = tf32r(t[threadIdx.x][threadIdx.y]);
}

__global__ void __launch_bounds__(256) round_a(const float4* __restrict__ in,
                                               float4* __restrict__ out) {
    int idx = blockIdx.x * 256 + threadIdx.x;
    float4 v = in[idx];
    v.x = tf32r(v.x); v.y = tf32r(v.y); v.z = tf32r(v.z); v.w = tf32r(v.w);
    out[idx] = v;
}

// ---------------------------------------------------------------------------
// tf32 GEMM: operands pre-rounded; BK=32; no cvt in loop.
// OMODE: 0 = plain row-major out; 1 = head-split out; 2 = head-split + rounded
// ---------------------------------------------------------------------------
template<int OMODE>
__global__ void __launch_bounds__(256, 2) gemm32(const float* __restrict__ A,
                                                 const float* __restrict__ B,
                                                 float* __restrict__ C) {
    extern __shared__ float smg[];
    const uint32_t sbase = smem_u32(smg);

    const int tid  = threadIdx.x;
    const int lane = tid & 31;
    const int warp = tid >> 5;
    const int wm   = warp & 1;
    const int wn   = warp >> 1;
    const int m0   = blockIdx.y * 128;
    const int n0   = blockIdx.x * 128;

    const float* Arow = A + (size_t)m0 * GKP;
    const float* Brow = B + (size_t)n0 * GKP;

    auto load_chunk = [&](int buf, int c) {
        const size_t kof = (size_t)c * BK2;
        const uint32_t dA = sbase + (buf ? 4608u : 0u) * 4u;
        const uint32_t dB = sbase + (buf ? 13824u : 9216u) * 4u;
#pragma unroll
        for (int u = 0; u < 4; u++) {
            int task = tid + u * 256;
            int row  = task >> 3;
            int seg  = task & 7;
            uint32_t so = (uint32_t)(row * STR2 + seg * 4) * 4;
            cp16(dA + so, Arow + (size_t)row * GKP + kof + seg * 4);
            cp16(dB + so, Brow + (size_t)row * GKP + kof + seg * 4);
        }
        cp_commit();
    };

    float acc[4][4][4];
#pragma unroll
    for (int i = 0; i < 4; i++)
#pragma unroll
        for (int j = 0; j < 4; j++)
#pragma unroll
            for (int r = 0; r < 4; r++) acc[i][j][r] = 0.f;

    load_chunk(0, 0);

    for (int c = 0; c < NCH2; c++) {
        const int buf = c & 1;
        if (c + 1 < NCH2) {
            load_chunk(buf ^ 1, c + 1);
            cp_wait<1>();
        } else {
            cp_wait<0>();
        }
        __syncthreads();

        const uint32_t sA = sbase + (buf ? 4608u : 0u) * 4u;
        const uint32_t sB = sbase + (buf ? 13824u : 9216u) * 4u;
        const uint32_t aBase = sA + (uint32_t)((wm * 64 + (lane & 15)) * STR2) * 4
                             + (lane >> 4) * 16;
        const uint32_t bBase = sB + (uint32_t)((wn * 32 + ((lane >> 4) & 1) * 8 + (lane & 7)) * STR2) * 4
                             + ((lane >> 3) & 1) * 16;
#pragma unroll
        for (int k8 = 0; k8 < 4; k8++) {
            const uint32_t kb = k8 * 32;
            uint32_t a[4][4];
#pragma unroll
            for (int mf = 0; mf < 4; mf++)
                ldsm4(a[mf][0], a[mf][1], a[mf][2], a[mf][3],
                      aBase + (uint32_t)(mf * 16 * STR2) * 4 + kb);
            uint32_t b[4][2];
#pragma unroll
            for (int bb = 0; bb < 2; bb++) {
                uint32_t r0, r1, r2, r3;
                ldsm4(r0, r1, r2, r3, bBase + (uint32_t)(bb * 16 * STR2) * 4 + kb);
                b[bb * 2 + 0][0] = r0; b[bb * 2 + 0][1] = r1;
                b[bb * 2 + 1][0] = r2; b[bb * 2 + 1][1] = r3;
            }
#pragma unroll
            for (int mf = 0; mf < 4; mf++)
#pragma unroll
                for (int nf = 0; nf < 4; nf++)
                    mma_tf32(acc[mf][nf], a[mf], b[nf]);
        }
        __syncthreads();
    }

    const int grp = lane >> 2;
    const int tg  = lane & 3;
#pragma unroll
    for (int mf = 0; mf < 4; mf++) {
#pragma unroll
        for (int nf = 0; nf < 4; nf++) {
            int n = n0 + wn * 32 + nf * 8 + tg * 2;
#pragma unroll
            for (int half = 0; half < 2; half++) {
                int m = m0 + wm * 64 + mf * 16 + grp + half * 8;
                float2 v = make_float2(acc[mf][nf][half * 2], acc[mf][nf][half * 2 + 1]);
                if (OMODE == 2) { v.x = tf32r(v.x); v.y = tf32r(v.y); }
                if (OMODE >= 1) {
                    int b_ = m >> 11, s_ = m & 2047;
                    int h_ = n >> 6,  hd = n & 63;
                    *(float2*)&C[((size_t)(b_ * HH + h_) * SS + s_) * HDD + hd] = v;
                } else {
                    *(float2*)&C[(size_t)m * DD + n] = v;
                }
            }
        }
    }
}

// ---------------------------------------------------------------------------
__device__ __forceinline__ float fast_exp(float x) {
    float t = fmaxf(x * 1.4426950408889634f, -126.0f);
    int   i = __float2int_rn(t);
    float f = t - (float)i;
    float p = 1.3333558146428443e-3f;
    p = fmaf(p, f, 9.6181291076284771e-3f);
    p = fmaf(p, f, 5.5504108664821580e-2f);
    p = fmaf(p, f, 2.4022650695910072e-1f);
    p = fmaf(p, f, 6.9314718055994531e-1f);
    p = fmaf(p, f, 1.0f);
    return p * __int_as_float((i + 127) << 23);
}

// ---------------------------------------------------------------------------
// Tensor-core flash attention v4: 128-row q tile, 8 warps, double-buffered K/V,
// one __syncthreads per key tile, heavy-batch-first scheduling.
// smem floats: Qh[128*ATS] Ql[128*ATS] Ps[128*ATS] Kh[2][64*ATS] Vt[2][64*ATS]
// ---------------------------------------------------------------------------
#define QROWS 128
#define KTILE (64*ATS)     // 4352 floats per K/V buffer

__global__ void __launch_bounds__(256) attn_mma(const int* __restrict__ valid_lens,
                                                float* __restrict__ out) {
    extern __shared__ float smf[];
    float* Qh = smf;                         // 128*ATS
    float* Ql = smf + QROWS*ATS;
    float* Ps = smf + 2*QROWS*ATS;
    float* Kb = smf + 3*QROWS*ATS;           // 2 x 64*ATS
    float* Vb = smf + 3*QROWS*ATS + 2*KTILE; // 2 x 64*ATS

    // ---- heavy-batch-first scheduling (deterministic) ----
    int vl[4];
#pragma unroll
    for (int i = 0; i < 4; i++) vl[i] = valid_lens[i];
    int ord[4] = {0, 1, 2, 3};
#pragma unroll
    for (int i = 0; i < 3; i++)
#pragma unroll
        for (int j = i + 1; j < 4; j++)
            if (vl[ord[j]] > vl[ord[i]]) { int t = ord[i]; ord[i] = ord[j]; ord[j] = t; }

    const int qt = blockIdx.x;               // 0..15
    const int b  = ord[blockIdx.y >> 4];     // rank -> batch
    const int h  = blockIdx.y & 15;
    const int vlen = vl[b];
    const int bh = b * HH + h;

    const float* q = g_q + (size_t)bh * (SS * HDD);
    const float* k = g_k + (size_t)bh * (SS * HDD);
    const float* v = g_v + (size_t)bh * (SS * HDD);

    const int tid  = threadIdx.x;
    const int lane = tid & 31;
    const int w    = tid >> 5;               // 0..7
    const int grp  = lane >> 2;
    const int tg   = lane & 3;

    // ---- stage Q (128x64) hi/lo ----
#pragma unroll
    for (int i = 0; i < 8; i++) {
        int idx = tid + i * 256;             // 0..2047 float4
        int row = idx >> 4, c4 = (idx & 15) << 2;
        float4 t = *(const float4*)&q[(size_t)(qt * QROWS + row) * HDD + c4];
        float4 hi, lo;
        hi.x = tf32r(t.x); lo.x = tf32r(t.x - hi.x);
        hi.y = tf32r(t.y); lo.y = tf32r(t.y - hi.y);
        hi.z = tf32r(t.z); lo.z = tf32r(t.z - hi.z);
        hi.w = tf32r(t.w); lo.w = tf32r(t.w - hi.w);
        *(float4*)&Qh[row * ATS + c4] = hi;
        *(float4*)&Ql[row * ATS + c4] = lo;
    }

    auto stage_kv = [&](int buf, int kt) {
        float* Kd = Kb + buf * KTILE;
        float* Vd = Vb + buf * KTILE;
#pragma unroll
        for (int i = 0; i < 4; i++) {
            int idx = tid + i * 256;         // 0..1023 float4
            int row = idx >> 4, c4 = (idx & 15) << 2;
            *(float4*)&Kd[row * ATS + c4] =
                *(const float4*)&k[(size_t)(kt * 64 + row) * HDD + c4];
        }
#pragma unroll
        for (int i = 0; i < 16; i++) {
            int idx = tid + i * 256;         // 0..4095
            int key = idx >> 6, hd = idx & 63;
            Vd[hd * ATS + key] = v[(size_t)(kt * 64 + key) * HDD + hd];
        }
    };

    float m_i[2] = {-1e30f, -1e30f}, l_i[2] = {0.f, 0.f};
    float O[8][4];
#pragma unroll
    for (int nf = 0; nf < 8; nf++)
#pragma unroll
        for (int r = 0; r < 4; r++) O[nf][r] = 0.f;

    const uint32_t sQh = smem_u32(Qh), sQl = smem_u32(Ql);
    const uint32_t sKb = smem_u32(Kb), sVb = smem_u32(Vb), sPs = smem_u32(Ps);
    const uint32_t aOff = (uint32_t)((w * 16 + (lane & 15)) * ATS) * 4 + (lane >> 4) * 16;
    const uint32_t bOff = (uint32_t)((((lane >> 4) & 1) * 8 + (lane & 7)) * ATS) * 4
                        + ((lane >> 3) & 1) * 16;

    const int ntiles = (vlen + 63) >> 6;
    stage_kv(0, 0);
    __syncthreads();

    for (int kt = 0; kt < ntiles; kt++) {
        const int buf = kt & 1;
        const uint32_t sK = sKb + (uint32_t)(buf * KTILE) * 4;
        const uint32_t sV = sVb + (uint32_t)(buf * KTILE) * 4;

        // ---- S = Qh K^T + Ql K^T ----
        float sacc[8][4];
#pragma unroll
        for (int nf = 0; nf < 8; nf++)
#pragma unroll
            for (int r = 0; r < 4; r++) sacc[nf][r] = 0.f;

#pragma unroll
        for (int k8 = 0; k8 < 8; k8++) {
            const uint32_t kb = k8 * 32;
            uint32_t qh[4], ql[4];
            ldsm4(qh[0], qh[1], qh[2], qh[3], sQh + aOff + kb);
            ldsm4(ql[0], ql[1], ql[2], ql[3], sQl + aOff + kb);
#pragma unroll
            for (int bbq = 0; bbq < 4; bbq++) {
                const uint32_t ro = (uint32_t)(bbq * 16 * ATS) * 4;
                uint32_t kh[4];
                ldsm4(kh[0], kh[1], kh[2], kh[3], sK + bOff + ro + kb);
                mma_tf32(sacc[bbq*2+0], qh, &kh[0]);
                mma_tf32(sacc[bbq*2+0], ql, &kh[0]);
                mma_tf32(sacc[bbq*2+1], qh, &kh[2]);
                mma_tf32(sacc[bbq*2+1], ql, &kh[2]);
            }
        }

        // ---- scale + mask ----
        const int kbase = kt * 64;
#pragma unroll
        for (int nf = 0; nf < 8; nf++) {
            int cg = kbase + nf * 8 + 2 * tg;
            bool mk0 = cg >= vlen, mk1 = (cg + 1) >= vlen;
#pragma unroll
            for (int hh = 0; hh < 2; hh++) {
                sacc[nf][hh*2+0] = mk0 ? -1e30f : sacc[nf][hh*2+0] * 0.125f;
                sacc[nf][hh*2+1] = mk1 ? -1e30f : sacc[nf][hh*2+1] * 0.125f;
            }
        }

        // ---- online softmax ----
#pragma unroll
        for (int hh = 0; hh < 2; hh++) {
            float mx = -1e30f;
#pragma unroll
            for (int nf = 0; nf < 8; nf++)
                mx = fmaxf(mx, fmaxf(sacc[nf][hh*2], sacc[nf][hh*2+1]));
            mx = fmaxf(mx, __shfl_xor_sync(0xffffffffu, mx, 1));
            mx = fmaxf(mx, __shfl_xor_sync(0xffffffffu, mx, 2));
            float m_new = fmaxf(m_i[hh], mx);
            float scl = fast_exp(m_i[hh] - m_new);
            m_i[hh] = m_new;
            float ps = 0.f;
            int prow = w * 16 + grp + hh * 8;
#pragma unroll
            for (int nf = 0; nf < 8; nf++) {
                float p0 = fast_exp(sacc[nf][hh*2+0] - m_new);
                float p1 = fast_exp(sacc[nf][hh*2+1] - m_new);
                ps += p0 + p1;
                *(float2*)&Ps[prow * ATS + nf * 8 + 2 * tg] =
                    make_float2(tf32r(p0), tf32r(p1));
            }
            ps += __shfl_xor_sync(0xffffffffu, ps, 1);
            ps += __shfl_xor_sync(0xffffffffu, ps, 2);
            l_i[hh] = l_i[hh] * scl + ps;
#pragma unroll
            for (int nf = 0; nf < 8; nf++) {
                O[nf][hh*2+0] *= scl;
                O[nf][hh*2+1] *= scl;
            }
        }
        __syncwarp();

        // ---- prefetch next K/V tile into other buffer (overlaps PV) ----
        if (kt + 1 < ntiles) stage_kv(buf ^ 1, kt + 1);

        // ---- O += P V ----
#pragma unroll
        for (int k8 = 0; k8 < 8; k8++) {
            const uint32_t kb = k8 * 32;
            uint32_t ap[4];
            ldsm4(ap[0], ap[1], ap[2], ap[3], sPs + aOff + kb);
#pragma unroll
            for (int bbv = 0; bbv < 4; bbv++) {
                uint32_t r0, r1, r2, r3;
                ldsm4(r0, r1, r2, r3, sV + bOff + (uint32_t)(bbv * 16 * ATS) * 4 + kb);
                uint32_t b0[2] = {r0, r1}, b1[2] = {r2, r3};
                mma_tf32(O[bbv*2+0], ap, b0);
                mma_tf32(O[bbv*2+1], ap, b1);
            }
        }
        __syncthreads();
    }

    // ---- epilogue (tf32-rounded; feeds Wo GEMM) ----
#pragma unroll
    for (int hh = 0; hh < 2; hh++) {
        float inv = 1.f / l_i[hh];
        int srow = qt * QROWS + w * 16 + grp + hh * 8;
#pragma unroll
        for (int nf = 0; nf < 8; nf++) {
            int hd = nf * 8 + 2 * tg;
            float2 val = make_float2(tf32r(O[nf][hh*2+0] * inv), tf32r(O[nf][hh*2+1] * inv));
            *(float2*)&out[((size_t)b * SS + srow) * DD + h * HDD + hd] = val;
        }
    }
}

// ---------------------------------------------------------------------------
extern "C" void kernel_launch(void* const* d_in, const int* in_sizes, int n_in,
                              void* d_out, int out_size) {
    (void)in_sizes; (void)n_in; (void)out_size;
    const float* queries    = (const float*)d_in[0];
    const float* keys       = (const float*)d_in[1];
    const float* values     = (const float*)d_in[2];
    const int*   valid_lens = (const int*)  d_in[3];
    const float* Wq         = (const float*)d_in[4];
    const float* Wk         = (const float*)d_in[5];
    const float* Wv         = (const float*)d_in[6];
    const float* Wo         = (const float*)d_in[7];
    float* out = (float*)d_out;

    float *pq, *pk, *pv, *pa, *pwt, *pat;
    cudaGetSymbolAddress((void**)&pq, g_q);
    cudaGetSymbolAddress((void**)&pk, g_k);
    cudaGetSymbolAddress((void**)&pv, g_v);
    cudaGetSymbolAddress((void**)&pa, g_attn);
    cudaGetSymbolAddress((void**)&pwt, g_wt);
    cudaGetSymbolAddress((void**)&pat, g_at);

    const int gemm_smem = 4 * 128 * STR2 * sizeof(float);     // 73728
    cudaFuncSetAttribute(gemm32<0>, cudaFuncAttributeMaxDynamicSharedMemorySize, gemm_smem);
    cudaFuncSetAttribute(gemm32<1>, cudaFuncAttributeMaxDynamicSharedMemorySize, gemm_smem);
    cudaFuncSetAttribute(gemm32<2>, cudaFuncAttributeMaxDynamicSharedMemorySize, gemm_smem);
    const int attn_smem = (3 * QROWS * ATS + 4 * KTILE) * sizeof(float);  // 174080
    cudaFuncSetAttribute(attn_mma, cudaFuncAttributeMaxDynamicSharedMemorySize, attn_smem);

    dim3 tw_grid(32, 32), tw_blk(32, 32);
    dim3 ra_grid(M_TOT * GKP / 4 / 256);
    dim3 gg(DD / 128, M_TOT / 128);
    dim3 gb(256);

    transpose_w<<<tw_grid, tw_blk>>>(Wq, pwt);
    round_a<<<ra_grid, 256>>>((const float4*)queries, (float4*)pat);
    gemm32<1><<<gg, gb, gemm_smem>>>(pat, pwt, pq);

    transpose_w<<<tw_grid, tw_blk>>>(Wk, pwt);
    round_a<<<ra_grid, 256>>>((const float4*)keys, (float4*)pat);
    gemm32<2><<<gg, gb, gemm_smem>>>(pat, pwt, pk);

    transpose_w<<<tw_grid, tw_blk>>>(Wv, pwt);
    round_a<<<ra_grid, 256>>>((const float4*)values, (float4*)pat);
    gemm32<2><<<gg, gb, gemm_smem>>>(pat, pwt, pv);

    dim3 agrid(SS / QROWS, BB * HH);   // (16, 64)
    attn_mma<<<agrid, 256, attn_smem>>>(valid_lens, pa);

    transpose_w<<<tw_grid, tw_blk>>>(Wo, pwt);
    gemm32<0><<<gg, gb, gemm_smem>>>(pa, pwt, out);
}

// round 10
// speedup vs baseline: 3.1311x; 1.1961x over previous
#include <cuda_runtime.h>
#include <math.h>
#include <stdint.h>

#define BB 4
#define SS 2048
#define DD 1024
#define HH 16
#define HDD 64
#define M_TOT (BB*SS)     // 8192
#define GKP 1024          // projection K
#define BK2 32            // k per chunk (gemm)
#define NCH2 (GKP/BK2)    // 32
#define STR2 36           // f32 per smem row (144B)
#define ATS 68            // f32 per smem row in attention (272B)
#define QROWS 64
#define KTILE (64*ATS)    // 4352 floats per K/V buffer

// ---------------------------------------------------------------------------
// scratch (__device__ globals; allocation-free)
// ---------------------------------------------------------------------------
__device__ float g_q[(size_t)BB*HH*SS*HDD];
__device__ float g_k[(size_t)BB*HH*SS*HDD];       // [bh][s][hd], tf32-rounded
__device__ float g_v[(size_t)BB*HH*SS*HDD];       // [bh][hd][s], tf32-rounded (transposed!)
__device__ float g_attn[(size_t)BB*SS*DD];        // tf32-rounded at attn epilogue
__device__ float g_wt[(size_t)4*DD*DD];           // 4 transposed+rounded weights
__device__ float g_at[(size_t)3*M_TOT*GKP];       // 3 rounded activations

// ---------------------------------------------------------------------------
// PTX helpers (baseline sm_80-level PTX only)
// ---------------------------------------------------------------------------
__device__ __forceinline__ uint32_t smem_u32(const void* p) {
    return (uint32_t)__cvta_generic_to_shared(p);
}
__device__ __forceinline__ void cp16(uint32_t dst, const void* src) {
    asm volatile("cp.async.cg.shared.global [%0], [%1], 16;" :: "r"(dst), "l"(src));
}
__device__ __forceinline__ void cp_commit() {
    asm volatile("cp.async.commit_group;" ::: "memory");
}
template<int N>
__device__ __forceinline__ void cp_wait() {
    asm volatile("cp.async.wait_group %0;" :: "n"(N) : "memory");
}
__device__ __forceinline__ void ldsm4(uint32_t& r0, uint32_t& r1, uint32_t& r2, uint32_t& r3,
                                      uint32_t addr) {
    asm volatile("ldmatrix.sync.aligned.m8n8.x4.shared.b16 {%0,%1,%2,%3}, [%4];"
                 : "=r"(r0), "=r"(r1), "=r"(r2), "=r"(r3) : "r"(addr));
}
__device__ __forceinline__ uint32_t to_tf32(uint32_t x) {
    uint32_t y;
    asm("cvt.rna.tf32.f32 %0, %1;" : "=r"(y) : "r"(x));
    return y;
}
__device__ __forceinline__ float tf32r(float x) {
    return __uint_as_float(to_tf32(__float_as_uint(x)));
}
__device__ __forceinline__ void mma_tf32(float* c, const uint32_t* a, const uint32_t* b) {
    asm volatile("mma.sync.aligned.m16n8k8.row.col.f32.tf32.tf32.f32 "
                 "{%0,%1,%2,%3}, {%4,%5,%6,%7}, {%8,%9}, {%0,%1,%2,%3};"
                 : "+f"(c[0]), "+f"(c[1]), "+f"(c[2]), "+f"(c[3])
                 : "r"(a[0]), "r"(a[1]), "r"(a[2]), "r"(a[3]), "r"(b[0]), "r"(b[1]));
}

// ---------------------------------------------------------------------------
// prep: all 4 weight transposes in one launch; all 3 activation roundings in one
// ---------------------------------------------------------------------------
__global__ void __launch_bounds__(1024) prep_w(const float* __restrict__ W0,
                                               const float* __restrict__ W1,
                                               const float* __restrict__ W2,
                                               const float* __restrict__ W3,
                                               float* __restrict__ WT) {
    __shared__ float t[32][33];
    const float* W = (blockIdx.z == 0) ? W0 : (blockIdx.z == 1) ? W1
                   : (blockIdx.z == 2) ? W2 : W3;
    float* out = WT + (size_t)blockIdx.z * DD * DD;
    int k0 = blockIdx.y * 32, n0 = blockIdx.x * 32;
    t[threadIdx.y][threadIdx.x] = W[(size_t)(k0 + threadIdx.y) * 1024 + n0 + threadIdx.x];
    __syncthreads();
    out[(size_t)(n0 + threadIdx.y) * 1024 + k0 + threadIdx.x] = tf32r(t[threadIdx.x][threadIdx.y]);
}

__global__ void __launch_bounds__(256) prep_a(const float4* __restrict__ A0,
                                              const float4* __restrict__ A1,
                                              const float4* __restrict__ A2,
                                              float4* __restrict__ out) {
    const float4* A = (blockIdx.z == 0) ? A0 : (blockIdx.z == 1) ? A1 : A2;
    int idx = blockIdx.x * 256 + threadIdx.x;
    float4 v = A[idx];
    v.x = tf32r(v.x); v.y = tf32r(v.y); v.z = tf32r(v.z); v.w = tf32r(v.w);
    out[(size_t)blockIdx.z * (M_TOT * GKP / 4) + idx] = v;
}

// ---------------------------------------------------------------------------
// tf32 GEMM: operands pre-rounded; BK=32; no cvt in loop.
// OMODE: 0 plain row-major; 1 head-split; 2 head-split+rounded;
//        3 head-TRANSPOSED ([bh][hd][s]) + rounded  (for V)
// ---------------------------------------------------------------------------
template<int OMODE>
__global__ void __launch_bounds__(256, 2) gemm32(const float* __restrict__ A,
                                                 const float* __restrict__ B,
                                                 float* __restrict__ C) {
    extern __shared__ float smg[];
    const uint32_t sbase = smem_u32(smg);

    const int tid  = threadIdx.x;
    const int lane = tid & 31;
    const int warp = tid >> 5;
    const int wm   = warp & 1;
    const int wn   = warp >> 1;
    const int m0   = blockIdx.y * 128;
    const int n0   = blockIdx.x * 128;

    const float* Arow = A + (size_t)m0 * GKP;
    const float* Brow = B + (size_t)n0 * GKP;

    auto load_chunk = [&](int buf, int c) {
        const size_t kof = (size_t)c * BK2;
        const uint32_t dA = sbase + (buf ? 4608u : 0u) * 4u;
        const uint32_t dB = sbase + (buf ? 13824u : 9216u) * 4u;
#pragma unroll
        for (int u = 0; u < 4; u++) {
            int task = tid + u * 256;
            int row  = task >> 3;
            int seg  = task & 7;
            uint32_t so = (uint32_t)(row * STR2 + seg * 4) * 4;
            cp16(dA + so, Arow + (size_t)row * GKP + kof + seg * 4);
            cp16(dB + so, Brow + (size_t)row * GKP + kof + seg * 4);
        }
        cp_commit();
    };

    float acc[4][4][4];
#pragma unroll
    for (int i = 0; i < 4; i++)
#pragma unroll
        for (int j = 0; j < 4; j++)
#pragma unroll
            for (int r = 0; r < 4; r++) acc[i][j][r] = 0.f;

    load_chunk(0, 0);

    for (int c = 0; c < NCH2; c++) {
        const int buf = c & 1;
        if (c + 1 < NCH2) {
            load_chunk(buf ^ 1, c + 1);
            cp_wait<1>();
        } else {
            cp_wait<0>();
        }
        __syncthreads();

        const uint32_t sA = sbase + (buf ? 4608u : 0u) * 4u;
        const uint32_t sB = sbase + (buf ? 13824u : 9216u) * 4u;
        const uint32_t aBase = sA + (uint32_t)((wm * 64 + (lane & 15)) * STR2) * 4
                             + (lane >> 4) * 16;
        const uint32_t bBase = sB + (uint32_t)((wn * 32 + ((lane >> 4) & 1) * 8 + (lane & 7)) * STR2) * 4
                             + ((lane >> 3) & 1) * 16;
#pragma unroll
        for (int k8 = 0; k8 < 4; k8++) {
            const uint32_t kb = k8 * 32;
            uint32_t a[4][4];
#pragma unroll
            for (int mf = 0; mf < 4; mf++)
                ldsm4(a[mf][0], a[mf][1], a[mf][2], a[mf][3],
                      aBase + (uint32_t)(mf * 16 * STR2) * 4 + kb);
            uint32_t b[4][2];
#pragma unroll
            for (int bb = 0; bb < 2; bb++) {
                uint32_t r0, r1, r2, r3;
                ldsm4(r0, r1, r2, r3, bBase + (uint32_t)(bb * 16 * STR2) * 4 + kb);
                b[bb * 2 + 0][0] = r0; b[bb * 2 + 0][1] = r1;
                b[bb * 2 + 1][0] = r2; b[bb * 2 + 1][1] = r3;
            }
#pragma unroll
            for (int mf = 0; mf < 4; mf++)
#pragma unroll
                for (int nf = 0; nf < 4; nf++)
                    mma_tf32(acc[mf][nf], a[mf], b[nf]);
        }
        __syncthreads();
    }

    const int grp = lane >> 2;
    const int tg  = lane & 3;
#pragma unroll
    for (int mf = 0; mf < 4; mf++) {
#pragma unroll
        for (int nf = 0; nf < 4; nf++) {
            int n = n0 + wn * 32 + nf * 8 + tg * 2;
#pragma unroll
            for (int half = 0; half < 2; half++) {
                int m = m0 + wm * 64 + mf * 16 + grp + half * 8;
                float2 v = make_float2(acc[mf][nf][half * 2], acc[mf][nf][half * 2 + 1]);
                if (OMODE >= 2) { v.x = tf32r(v.x); v.y = tf32r(v.y); }
                if (OMODE == 3) {
                    int b_ = m >> 11, s_ = m & 2047;
                    int h_ = n >> 6,  hd = n & 63;
                    size_t base = ((size_t)(b_ * HH + h_) * HDD + hd) * SS + s_;
                    C[base]      = v.x;
                    C[base + SS] = v.y;
                } else if (OMODE >= 1) {
                    int b_ = m >> 11, s_ = m & 2047;
                    int h_ = n >> 6,  hd = n & 63;
                    *(float2*)&C[((size_t)(b_ * HH + h_) * SS + s_) * HDD + hd] = v;
                } else {
                    *(float2*)&C[(size_t)m * DD + n] = v;
                }
            }
        }
    }
}

// ---------------------------------------------------------------------------
__device__ __forceinline__ float fast_exp(float x) {
    float t = fmaxf(x * 1.4426950408889634f, -126.0f);
    int   i = __float2int_rn(t);
    float f = t - (float)i;
    float p = 1.3333558146428443e-3f;
    p = fmaf(p, f, 9.6181291076284771e-3f);
    p = fmaf(p, f, 5.5504108664821580e-2f);
    p = fmaf(p, f, 2.4022650695910072e-1f);
    p = fmaf(p, f, 6.9314718055994531e-1f);
    p = fmaf(p, f, 1.0f);
    return p * __int_as_float((i + 127) << 23);
}

// ---------------------------------------------------------------------------
// Flash attention v5: 64 q rows / 4 warps / 128 thr; S = Qh*Kh single term;
// K and V staged by pure cp.async (V pre-transposed in gmem); double buffer;
// one __syncthreads per tile. smem = 104448 B -> 2 CTAs/SM.
// smem floats: Qh@0, Ps@4352, Kb@8704 (2 bufs), Vb@17408 (2 bufs)
// ---------------------------------------------------------------------------
__global__ void __launch_bounds__(128) attn_mma(const int* __restrict__ valid_lens,
                                                float* __restrict__ out) {
    extern __shared__ float smf[];
    float* Qh = smf;
    float* Ps = smf + KTILE;

    // heavy-batch-first scheduling
    int vl[4];
#pragma unroll
    for (int i = 0; i < 4; i++) vl[i] = valid_lens[i];
    int ord[4] = {0, 1, 2, 3};
#pragma unroll
    for (int i = 0; i < 3; i++)
#pragma unroll
        for (int j = i + 1; j < 4; j++)
            if (vl[ord[j]] > vl[ord[i]]) { int t = ord[i]; ord[i] = ord[j]; ord[j] = t; }

    const int qt = blockIdx.x;               // 0..31
    const int b  = ord[blockIdx.y >> 4];
    const int h  = blockIdx.y & 15;
    const int vlen = vl[b];
    const int bh = b * HH + h;

    const float* q = g_q + (size_t)bh * (SS * HDD);
    const float* k = g_k + (size_t)bh * (SS * HDD);
    const float* v = g_v + (size_t)bh * (HDD * SS);   // [hd][s]

    const int tid  = threadIdx.x;
    const int lane = tid & 31;
    const int w    = tid >> 5;               // 0..3
    const int grp  = lane >> 2;
    const int tg   = lane & 3;

    const uint32_t sQh = smem_u32(Qh);
    const uint32_t sPs = smem_u32(Ps);
    const uint32_t sKb = sQh + 8704u * 4u;
    const uint32_t sVb = sQh + 17408u * 4u;

    // stage Q (rounded hi only)
#pragma unroll
    for (int i = 0; i < 8; i++) {
        int idx = tid + i * 128;             // 0..1023 float4
        int row = idx >> 4, c4 = (idx & 15) << 2;
        float4 t = *(const float4*)&q[(size_t)(qt * QROWS + row) * HDD + c4];
        t.x = tf32r(t.x); t.y = tf32r(t.y); t.z = tf32r(t.z); t.w = tf32r(t.w);
        *(float4*)&Qh[row * ATS + c4] = t;
    }

    // cp.async staging of one K/V tile pair
    auto stage_kv = [&](int buf, int kt) {
        const uint32_t dK = sKb + (uint32_t)(buf * KTILE) * 4u;
        const uint32_t dV = sVb + (uint32_t)(buf * KTILE) * 4u;
        const int kof = kt * 64;
#pragma unroll
        for (int i = 0; i < 8; i++) {
            int task = tid + i * 128;        // 0..1023
            int row = task >> 4, seg = task & 15;
            cp16(dK + (uint32_t)(row * ATS + seg * 4) * 4,
                 k + (size_t)(kof + row) * HDD + seg * 4);
            cp16(dV + (uint32_t)(row * ATS + seg * 4) * 4,
                 v + (size_t)row * SS + kof + seg * 4);
        }
        cp_commit();
    };

    float m_i[2] = {-1e30f, -1e30f}, l_i[2] = {0.f, 0.f};
    float O[8][4];
#pragma unroll
    for (int nf = 0; nf < 8; nf++)
#pragma unroll
        for (int r = 0; r < 4; r++) O[nf][r] = 0.f;

    const uint32_t aOff = (uint32_t)((w * 16 + (lane & 15)) * ATS) * 4 + (lane >> 4) * 16;
    const uint32_t bOff = (uint32_t)((((lane >> 4) & 1) * 8 + (lane & 7)) * ATS) * 4
                        + ((lane >> 3) & 1) * 16;

    const int ntiles = (vlen + 63) >> 6;
    stage_kv(0, 0);

    for (int kt = 0; kt < ntiles; kt++) {
        const int buf = kt & 1;
        cp_wait<0>();
        __syncthreads();
        // prefetch next tile immediately (overlaps whole tile compute)
        if (kt + 1 < ntiles) stage_kv(buf ^ 1, kt + 1);

        const uint32_t sK = sKb + (uint32_t)(buf * KTILE) * 4u;
        const uint32_t sV = sVb + (uint32_t)(buf * KTILE) * 4u;

        // ---- S = Qh K^T ----
        float sacc[8][4];
#pragma unroll
        for (int nf = 0; nf < 8; nf++)
#pragma unroll
            for (int r = 0; r < 4; r++) sacc[nf][r] = 0.f;

#pragma unroll
        for (int k8 = 0; k8 < 8; k8++) {
            const uint32_t kb = k8 * 32;
            uint32_t qh[4];
            ldsm4(qh[0], qh[1], qh[2], qh[3], sQh + aOff + kb);
#pragma unroll
            for (int bbq = 0; bbq < 4; bbq++) {
                uint32_t kh[4];
                ldsm4(kh[0], kh[1], kh[2], kh[3],
                      sK + bOff + (uint32_t)(bbq * 16 * ATS) * 4 + kb);
                mma_tf32(sacc[bbq*2+0], qh, &kh[0]);
                mma_tf32(sacc[bbq*2+1], qh, &kh[2]);
            }
        }

        // ---- scale + mask ----
        const int kbase = kt * 64;
#pragma unroll
        for (int nf = 0; nf < 8; nf++) {
            int cg = kbase + nf * 8 + 2 * tg;
            bool mk0 = cg >= vlen, mk1 = (cg + 1) >= vlen;
#pragma unroll
            for (int hh = 0; hh < 2; hh++) {
                sacc[nf][hh*2+0] = mk0 ? -1e30f : sacc[nf][hh*2+0] * 0.125f;
                sacc[nf][hh*2+1] = mk1 ? -1e30f : sacc[nf][hh*2+1] * 0.125f;
            }
        }

        // ---- online softmax ----
#pragma unroll
        for (int hh = 0; hh < 2; hh++) {
            float mx = -1e30f;
#pragma unroll
            for (int nf = 0; nf < 8; nf++)
                mx = fmaxf(mx, fmaxf(sacc[nf][hh*2], sacc[nf][hh*2+1]));
            mx = fmaxf(mx, __shfl_xor_sync(0xffffffffu, mx, 1));
            mx = fmaxf(mx, __shfl_xor_sync(0xffffffffu, mx, 2));
            float m_new = fmaxf(m_i[hh], mx);
            float scl = fast_exp(m_i[hh] - m_new);
            m_i[hh] = m_new;
            float ps = 0.f;
            int prow = w * 16 + grp + hh * 8;
#pragma unroll
            for (int nf = 0; nf < 8; nf++) {
                float p0 = fast_exp(sacc[nf][hh*2+0] - m_new);
                float p1 = fast_exp(sacc[nf][hh*2+1] - m_new);
                ps += p0 + p1;
                *(float2*)&Ps[prow * ATS + nf * 8 + 2 * tg] =
                    make_float2(tf32r(p0), tf32r(p1));
            }
            ps += __shfl_xor_sync(0xffffffffu, ps, 1);
            ps += __shfl_xor_sync(0xffffffffu, ps, 2);
            l_i[hh] = l_i[hh] * scl + ps;
#pragma unroll
            for (int nf = 0; nf < 8; nf++) {
                O[nf][hh*2+0] *= scl;
                O[nf][hh*2+1] *= scl;
            }
        }
        __syncwarp();

        // ---- O += P V ----
#pragma unroll
        for (int k8 = 0; k8 < 8; k8++) {
            const uint32_t kb = k8 * 32;
            uint32_t ap[4];
            ldsm4(ap[0], ap[1], ap[2], ap[3], sPs + aOff + kb);
#pragma unroll
            for (int bbv = 0; bbv < 4; bbv++) {
                uint32_t r0, r1, r2, r3;
                ldsm4(r0, r1, r2, r3, sV + bOff + (uint32_t)(bbv * 16 * ATS) * 4 + kb);
                uint32_t b0[2] = {r0, r1}, b1[2] = {r2, r3};
                mma_tf32(O[bbv*2+0], ap, b0);
                mma_tf32(O[bbv*2+1], ap, b1);
            }
        }
    }

    // ---- epilogue (tf32-rounded; feeds Wo GEMM) ----
#pragma unroll
    for (int hh = 0; hh < 2; hh++) {
        float inv = 1.f / l_i[hh];
        int srow = qt * QROWS + w * 16 + grp + hh * 8;
#pragma unroll
        for (int nf = 0; nf < 8; nf++) {
            int hd = nf * 8 + 2 * tg;
            float2 val = make_float2(tf32r(O[nf][hh*2+0] * inv), tf32r(O[nf][hh*2+1] * inv));
            *(float2*)&out[((size_t)b * SS + srow) * DD + h * HDD + hd] = val;
        }
    }
}

// ---------------------------------------------------------------------------
extern "C" void kernel_launch(void* const* d_in, const int* in_sizes, int n_in,
                              void* d_out, int out_size) {
    (void)in_sizes; (void)n_in; (void)out_size;
    const float* queries    = (const float*)d_in[0];
    const float* keys       = (const float*)d_in[1];
    const float* values     = (const float*)d_in[2];
    const int*   valid_lens = (const int*)  d_in[3];
    const float* Wq         = (const float*)d_in[4];
    const float* Wk         = (const float*)d_in[5];
    const float* Wv         = (const float*)d_in[6];
    const float* Wo         = (const float*)d_in[7];
    float* out = (float*)d_out;

    float *pq, *pk, *pv, *pa, *pwt, *pat;
    cudaGetSymbolAddress((void**)&pq, g_q);
    cudaGetSymbolAddress((void**)&pk, g_k);
    cudaGetSymbolAddress((void**)&pv, g_v);
    cudaGetSymbolAddress((void**)&pa, g_attn);
    cudaGetSymbolAddress((void**)&pwt, g_wt);
    cudaGetSymbolAddress((void**)&pat, g_at);

    const int gemm_smem = 4 * 128 * STR2 * sizeof(float);     // 73728
    cudaFuncSetAttribute(gemm32<0>, cudaFuncAttributeMaxDynamicSharedMemorySize, gemm_smem);
    cudaFuncSetAttribute(gemm32<1>, cudaFuncAttributeMaxDynamicSharedMemorySize, gemm_smem);
    cudaFuncSetAttribute(gemm32<2>, cudaFuncAttributeMaxDynamicSharedMemorySize, gemm_smem);
    cudaFuncSetAttribute(gemm32<3>, cudaFuncAttributeMaxDynamicSharedMemorySize, gemm_smem);
    const int attn_smem = (2 * KTILE + 4 * KTILE) * sizeof(float);   // 104448
    cudaFuncSetAttribute(attn_mma, cudaFuncAttributeMaxDynamicSharedMemorySize, attn_smem);

    const size_t AQ = (size_t)M_TOT * GKP;
    const size_t WQ = (size_t)DD * DD;

    // launch 1: all weight transposes; launch 2: all activation roundings
    dim3 pw_grid(32, 32, 4), pw_blk(32, 32);
    prep_w<<<pw_grid, pw_blk>>>(Wq, Wk, Wv, Wo, pwt);
    dim3 pa_grid(M_TOT * GKP / 4 / 256, 1, 3);
    prep_a<<<pa_grid, 256>>>((const float4*)queries, (const float4*)keys,
                             (const float4*)values, (float4*)pat);

    dim3 gg(DD / 128, M_TOT / 128);
    dim3 gb(256);
    // launches 3-5: projections
    gemm32<1><<<gg, gb, gemm_smem>>>(pat,          pwt,          pq);
    gemm32<2><<<gg, gb, gemm_smem>>>(pat + AQ,     pwt + WQ,     pk);
    gemm32<3><<<gg, gb, gemm_smem>>>(pat + 2 * AQ, pwt + 2 * WQ, pv);

    // launch 6: attention (ncu capture slot)
    dim3 agrid(SS / QROWS, BB * HH);   // (32, 64)
    attn_mma<<<agrid, 128, attn_smem>>>(valid_lens, pa);

    // launch 7: output projection
    gemm32<0><<<gg, gb, gemm_smem>>>(pa, pwt + 3 * WQ, out);
}